// round 9
// baseline (speedup 1.0000x reference)
#include <cuda_runtime.h>
#include <cuda_bf16.h>
#include <cstdint>
#include <cstddef>

// ---------------------------------------------------------------------------
// SimplePointNetCPL — layer3 via 3xTF32 (feeds argmax, flip-safe);
// critical GEMM via bf16x3 m16n8k16 with K=32 tiles (halved sync overhead).
// ---------------------------------------------------------------------------

#define BATCH     64
#define NPTS      1024
#define CPLK      256
#define NCLS      40
#define BN_EPS    1e-5f
#define CPL_EPS   1e-7f

#define MROWS     (BATCH * NPTS)    // 65536
#define MCRIT     (BATCH * CPLK)    // 16384

// ------------------------------- scratch -----------------------------------
__device__ float g_Z1[MROWS * 64];
__device__ float g_Z2[MROWS * 128];
__device__ float g_Z3[(size_t)MROWS * 1024];
__device__ float g_CR[(size_t)MCRIT * 1024];
__device__ float g_ZC[(size_t)MCRIT * 1024];
__device__ float g_PS[64 * 1024];
__device__ float g_PQ[64 * 1024];
__device__ float g_S1[64],  g_H1[64];
__device__ float g_S2[128], g_H2[128];
__device__ float g_S3[1024], g_H3[1024];
__device__ float g_SC[1024], g_HC[1024];
__device__ float g_SF1[512], g_HF1[512];
__device__ float g_SF2[256], g_HF2[256];
__device__ int   g_IDX[BATCH * CPLK];
__device__ float g_GF[BATCH * 1024];
__device__ float g_O1[BATCH * 512];
__device__ float g_O2[BATCH * 256];
__device__ float g_BMAX[BATCH * 1024];
__device__ int   g_BIDX[BATCH * 1024];

// ------------------------- layer 1 (K=3 micro GEMM) -------------------------
__global__ void __launch_bounds__(256) l1_kernel(const float* __restrict__ x,
                                                 const float* __restrict__ W1,
                                                 float* __restrict__ Z1) {
    __shared__ float w[64 * 3];
    if (threadIdx.x < 192) w[threadIdx.x] = W1[threadIdx.x];
    __syncthreads();
    int r = blockIdx.x * 4 + (threadIdx.x >> 6);
    int c = threadIdx.x & 63;
    float x0 = x[r * 3 + 0], x1 = x[r * 3 + 1], x2 = x[r * 3 + 2];
    Z1[(size_t)r * 64 + c] = x0 * w[c * 3 + 0] + x1 * w[c * 3 + 1] + x2 * w[c * 3 + 2];
}

// --------------------------- column statistics ------------------------------
__global__ void colstats1(const float* __restrict__ Z, int M, int N,
                          float* __restrict__ ps, float* __restrict__ pq) {
    int col = blockIdx.x * 32 + threadIdx.x;
    int chunk = M >> 6;
    int r0 = blockIdx.y * chunk;
    float s = 0.f, q = 0.f;
    for (int r = r0 + threadIdx.y; r < r0 + chunk; r += 8) {
        float v = Z[(size_t)r * N + col];
        s += v; q += v * v;
    }
    __shared__ float ss[8][32], qq[8][32];
    ss[threadIdx.y][threadIdx.x] = s;
    qq[threadIdx.y][threadIdx.x] = q;
    __syncthreads();
    if (threadIdx.y == 0) {
        for (int t = 1; t < 8; t++) { s += ss[t][threadIdx.x]; q += qq[t][threadIdx.x]; }
        ps[blockIdx.y * N + col] = s;
        pq[blockIdx.y * N + col] = q;
    }
}

// Z3 variant: also emits per-(batch,channel) raw max + first-argmax.
__global__ void colstats1_cpl(const float* __restrict__ Z,
                              float* __restrict__ ps, float* __restrict__ pq,
                              float* __restrict__ bmax, int* __restrict__ bidx) {
    int col = blockIdx.x * 32 + threadIdx.x;
    int b = blockIdx.y;
    const float* p = Z + ((size_t)b * NPTS) * 1024 + col;
    float s = 0.f, q = 0.f;
    float mv = -3.4e38f; int mi = 0;
    for (int r = threadIdx.y; r < NPTS; r += 8) {
        float v = p[(size_t)r << 10];
        s += v; q += v * v;
        if (v > mv) { mv = v; mi = r; }
    }
    __shared__ float ss[8][32], qq[8][32], mm[8][32];
    __shared__ int   ii[8][32];
    ss[threadIdx.y][threadIdx.x] = s;
    qq[threadIdx.y][threadIdx.x] = q;
    mm[threadIdx.y][threadIdx.x] = mv;
    ii[threadIdx.y][threadIdx.x] = mi;
    __syncthreads();
    if (threadIdx.y == 0) {
        for (int t = 1; t < 8; t++) {
            s += ss[t][threadIdx.x]; q += qq[t][threadIdx.x];
            float tv = mm[t][threadIdx.x]; int ti = ii[t][threadIdx.x];
            if (tv > mv || (tv == mv && ti < mi)) { mv = tv; mi = ti; }
        }
        ps[b * 1024 + col] = s;
        pq[b * 1024 + col] = q;
        bmax[b * 1024 + col] = mv;
        bidx[b * 1024 + col] = mi;
    }
}

__global__ void colstats2(const float* __restrict__ ps, const float* __restrict__ pq,
                          int M, int N,
                          const float* __restrict__ gam, const float* __restrict__ bet,
                          float* __restrict__ scale, float* __restrict__ shift) {
    int col = blockIdx.x * 256 + threadIdx.x;
    if (col >= N) return;
    float s = 0.f, q = 0.f;
    for (int rb = 0; rb < 64; rb++) { s += ps[rb * N + col]; q += pq[rb * N + col]; }
    float mean = s / (float)M;
    float var  = q / (float)M - mean * mean;
    float sc = gam[col] * rsqrtf(var + BN_EPS);
    scale[col] = sc;
    shift[col] = bet[col] - mean * sc;
}

__global__ void colstats_small(const float* __restrict__ Z, int M, int N,
                               const float* __restrict__ gam, const float* __restrict__ bet,
                               float* __restrict__ scale, float* __restrict__ shift) {
    int col = blockIdx.x * 256 + threadIdx.x;
    if (col >= N) return;
    float s = 0.f, q = 0.f;
    for (int r = 0; r < M; r++) { float v = Z[(size_t)r * N + col]; s += v; q += v * v; }
    float mean = s / (float)M;
    float var  = q / (float)M - mean * mean;
    float sc = gam[col] * rsqrtf(var + BN_EPS);
    scale[col] = sc;
    shift[col] = bet[col] - mean * sc;
}

// ------------------------------- fp32 SGEMM (layer 2) -----------------------
template<bool ACT>
__global__ void __launch_bounds__(256) sgemm_kernel(
    const float* __restrict__ A, const float* __restrict__ W,
    const float* __restrict__ scale, const float* __restrict__ shift,
    float* __restrict__ C, int M, int N, int K)
{
    __shared__ float As[8][128];
    __shared__ float Bs[8][128];
    int tid = threadIdx.x;
    int tx = tid & 15, ty = tid >> 4;
    int row0 = blockIdx.y * 128;
    int col0 = blockIdx.x * 128;

    int lr = tid >> 1;
    int lk = (tid & 1) * 4;

    const float* Aptr = A + (size_t)(row0 + lr) * K + lk;
    const float* Wptr = W + (size_t)(col0 + lr) * K + lk;

    float acc[8][8];
    #pragma unroll
    for (int i = 0; i < 8; i++)
        #pragma unroll
        for (int j = 0; j < 8; j++) acc[i][j] = 0.f;

    for (int kk = 0; kk < K; kk += 8) {
        float4 av = *(const float4*)(Aptr + kk);
        float4 wv = *(const float4*)(Wptr + kk);
        if (ACT) {
            float4 sv = *(const float4*)(scale + kk + lk);
            float4 hv = *(const float4*)(shift + kk + lk);
            av.x = fmaxf(av.x * sv.x + hv.x, 0.f);
            av.y = fmaxf(av.y * sv.y + hv.y, 0.f);
            av.z = fmaxf(av.z * sv.z + hv.z, 0.f);
            av.w = fmaxf(av.w * sv.w + hv.w, 0.f);
        }
        As[lk + 0][lr] = av.x; As[lk + 1][lr] = av.y;
        As[lk + 2][lr] = av.z; As[lk + 3][lr] = av.w;
        Bs[lk + 0][lr] = wv.x; Bs[lk + 1][lr] = wv.y;
        Bs[lk + 2][lr] = wv.z; Bs[lk + 3][lr] = wv.w;
        __syncthreads();
        #pragma unroll
        for (int k = 0; k < 8; k++) {
            float4 a0 = *(const float4*)&As[k][ty * 4];
            float4 a1 = *(const float4*)&As[k][ty * 4 + 64];
            float4 b0 = *(const float4*)&Bs[k][tx * 4];
            float4 b1 = *(const float4*)&Bs[k][tx * 4 + 64];
            float ar[8] = {a0.x, a0.y, a0.z, a0.w, a1.x, a1.y, a1.z, a1.w};
            float br[8] = {b0.x, b0.y, b0.z, b0.w, b1.x, b1.y, b1.z, b1.w};
            #pragma unroll
            for (int i = 0; i < 8; i++)
                #pragma unroll
                for (int j = 0; j < 8; j++)
                    acc[i][j] += ar[i] * br[j];
        }
        __syncthreads();
    }

    #pragma unroll
    for (int i = 0; i < 8; i++) {
        int r = row0 + ty * 4 + ((i < 4) ? i : 64 + (i - 4));
        float4 v0 = {acc[i][0], acc[i][1], acc[i][2], acc[i][3]};
        float4 v1 = {acc[i][4], acc[i][5], acc[i][6], acc[i][7]};
        *(float4*)&C[(size_t)r * N + col0 + tx * 4]      = v0;
        *(float4*)&C[(size_t)r * N + col0 + tx * 4 + 64] = v1;
    }
}

// ---------------------- shared helpers for MMA kernels -----------------------
#define TBK 16
#define SPITCH 20
#define RAWP 20
#define PLANE  (128 * SPITCH)
#define RAWSZ  (128 * RAWP)
#define G3X_SMEM ((4 * PLANE + 2 * RAWSZ) * 4)   // 61440 bytes (tf32 kernel)

__device__ __forceinline__ float tf32r(float x) {
    unsigned u;
    asm("cvt.rna.tf32.f32 %0, %1;" : "=r"(u) : "f"(x));
    return __uint_as_float(u);
}

__device__ __forceinline__ void mma_tf32(float* c, const unsigned* a, const unsigned* b) {
    asm volatile(
        "mma.sync.aligned.m16n8k8.row.col.f32.tf32.tf32.f32 "
        "{%0,%1,%2,%3}, {%4,%5,%6,%7}, {%8,%9}, {%0,%1,%2,%3};\n"
        : "+f"(c[0]), "+f"(c[1]), "+f"(c[2]), "+f"(c[3])
        : "r"(a[0]), "r"(a[1]), "r"(a[2]), "r"(a[3]), "r"(b[0]), "r"(b[1]));
}

__device__ __forceinline__ void mma_bf16(float* c, const unsigned* a, const unsigned* b) {
    asm volatile(
        "mma.sync.aligned.m16n8k16.row.col.f32.bf16.bf16.f32 "
        "{%0,%1,%2,%3}, {%4,%5,%6,%7}, {%8,%9}, {%0,%1,%2,%3};\n"
        : "+f"(c[0]), "+f"(c[1]), "+f"(c[2]), "+f"(c[3])
        : "r"(a[0]), "r"(a[1]), "r"(a[2]), "r"(a[3]), "r"(b[0]), "r"(b[1]));
}

__device__ __forceinline__ void cp_async16(uint32_t dst, const void* src) {
    asm volatile("cp.async.ca.shared.global [%0], [%1], 16;\n" :: "r"(dst), "l"(src));
}

// pack two floats into bf16x2 word (low = first), and its residual word
__device__ __forceinline__ void bfsplit2(float v0, float v1, unsigned& big, unsigned& small) {
    __nv_bfloat16 b0 = __float2bfloat16_rn(v0);
    __nv_bfloat16 b1 = __float2bfloat16_rn(v1);
    __nv_bfloat16 s0 = __float2bfloat16_rn(v0 - __bfloat162float(b0));
    __nv_bfloat16 s1 = __float2bfloat16_rn(v1 - __bfloat162float(b1));
    unsigned ub0 = (unsigned)__bfloat16_as_ushort(b0);
    unsigned ub1 = (unsigned)__bfloat16_as_ushort(b1);
    unsigned us0 = (unsigned)__bfloat16_as_ushort(s0);
    unsigned us1 = (unsigned)__bfloat16_as_ushort(s1);
    big   = ub0 | (ub1 << 16);
    small = us0 | (us1 << 16);
}

// ------------------------------ 3xTF32 GEMM (layer 3) ------------------------
// R6 engine: split-at-store planes + cp.async raw staging.
template<bool ACT>
__global__ void __launch_bounds__(256, 2) gemm3x_kernel(
    const float* __restrict__ A, const float* __restrict__ W,
    const float* __restrict__ scale, const float* __restrict__ shift,
    float* __restrict__ C, int M, int N, int K)
{
    extern __shared__ float sm[];
    float* asb = sm;
    float* ass = sm + PLANE;
    float* bsb = sm + 2 * PLANE;
    float* bss = sm + 3 * PLANE;
    float* rawA = sm + 4 * PLANE;
    float* rawB = rawA + RAWSZ;

    int tid = threadIdx.x;
    int lane = tid & 31, wid = tid >> 5;
    int warp_m = (wid >> 2) * 64, warp_n = (wid & 3) * 32;
    int qr = lane >> 2, qc = lane & 3;
    int row0 = blockIdx.y * 128, col0 = blockIdx.x * 128;

    int lrow = tid >> 2;
    int lcol = (tid & 3) * 4;

    const float* Ap0 = A + (size_t)(row0 + lrow) * K + lcol;
    const float* Ap1 = A + (size_t)(row0 + lrow + 64) * K + lcol;
    const float* Wp0 = W + (size_t)(col0 + lrow) * K + lcol;
    const float* Wp1 = W + (size_t)(col0 + lrow + 64) * K + lcol;

    uint32_t rA0 = (uint32_t)__cvta_generic_to_shared(rawA + lrow * RAWP + lcol);
    uint32_t rA1 = (uint32_t)__cvta_generic_to_shared(rawA + (lrow + 64) * RAWP + lcol);
    uint32_t rB0 = (uint32_t)__cvta_generic_to_shared(rawB + lrow * RAWP + lcol);
    uint32_t rB1 = (uint32_t)__cvta_generic_to_shared(rawB + (lrow + 64) * RAWP + lcol);

    float acc[4][4][4];
    #pragma unroll
    for (int i = 0; i < 4; i++)
        #pragma unroll
        for (int j = 0; j < 4; j++)
            #pragma unroll
            for (int r = 0; r < 4; r++) acc[i][j][r] = 0.f;

    auto fetch = [&](int kk) {
        cp_async16(rA0, Ap0 + kk);
        cp_async16(rA1, Ap1 + kk);
        cp_async16(rB0, Wp0 + kk);
        cp_async16(rB1, Wp1 + kk);
        asm volatile("cp.async.commit_group;\n");
    };
    auto split_store = [&](int kk) {
        float4 a0 = *(const float4*)(rawA + lrow * RAWP + lcol);
        float4 a1 = *(const float4*)(rawA + (lrow + 64) * RAWP + lcol);
        float4 b0 = *(const float4*)(rawB + lrow * RAWP + lcol);
        float4 b1 = *(const float4*)(rawB + (lrow + 64) * RAWP + lcol);
        if (ACT) {
            float4 sv = *(const float4*)(scale + kk + lcol);
            float4 hv = *(const float4*)(shift + kk + lcol);
            a0.x = fmaxf(a0.x * sv.x + hv.x, 0.f);
            a0.y = fmaxf(a0.y * sv.y + hv.y, 0.f);
            a0.z = fmaxf(a0.z * sv.z + hv.z, 0.f);
            a0.w = fmaxf(a0.w * sv.w + hv.w, 0.f);
            a1.x = fmaxf(a1.x * sv.x + hv.x, 0.f);
            a1.y = fmaxf(a1.y * sv.y + hv.y, 0.f);
            a1.z = fmaxf(a1.z * sv.z + hv.z, 0.f);
            a1.w = fmaxf(a1.w * sv.w + hv.w, 0.f);
        }
        float b;
        b = tf32r(a0.x); asb[lrow*SPITCH+lcol+0] = b; ass[lrow*SPITCH+lcol+0] = tf32r(a0.x - b);
        b = tf32r(a0.y); asb[lrow*SPITCH+lcol+1] = b; ass[lrow*SPITCH+lcol+1] = tf32r(a0.y - b);
        b = tf32r(a0.z); asb[lrow*SPITCH+lcol+2] = b; ass[lrow*SPITCH+lcol+2] = tf32r(a0.z - b);
        b = tf32r(a0.w); asb[lrow*SPITCH+lcol+3] = b; ass[lrow*SPITCH+lcol+3] = tf32r(a0.w - b);
        b = tf32r(a1.x); asb[(lrow+64)*SPITCH+lcol+0] = b; ass[(lrow+64)*SPITCH+lcol+0] = tf32r(a1.x - b);
        b = tf32r(a1.y); asb[(lrow+64)*SPITCH+lcol+1] = b; ass[(lrow+64)*SPITCH+lcol+1] = tf32r(a1.y - b);
        b = tf32r(a1.z); asb[(lrow+64)*SPITCH+lcol+2] = b; ass[(lrow+64)*SPITCH+lcol+2] = tf32r(a1.z - b);
        b = tf32r(a1.w); asb[(lrow+64)*SPITCH+lcol+3] = b; ass[(lrow+64)*SPITCH+lcol+3] = tf32r(a1.w - b);
        b = tf32r(b0.x); bsb[lrow*SPITCH+lcol+0] = b; bss[lrow*SPITCH+lcol+0] = tf32r(b0.x - b);
        b = tf32r(b0.y); bsb[lrow*SPITCH+lcol+1] = b; bss[lrow*SPITCH+lcol+1] = tf32r(b0.y - b);
        b = tf32r(b0.z); bsb[lrow*SPITCH+lcol+2] = b; bss[lrow*SPITCH+lcol+2] = tf32r(b0.z - b);
        b = tf32r(b0.w); bsb[lrow*SPITCH+lcol+3] = b; bss[lrow*SPITCH+lcol+3] = tf32r(b0.w - b);
        b = tf32r(b1.x); bsb[(lrow+64)*SPITCH+lcol+0] = b; bss[(lrow+64)*SPITCH+lcol+0] = tf32r(b1.x - b);
        b = tf32r(b1.y); bsb[(lrow+64)*SPITCH+lcol+1] = b; bss[(lrow+64)*SPITCH+lcol+1] = tf32r(b1.y - b);
        b = tf32r(b1.z); bsb[(lrow+64)*SPITCH+lcol+2] = b; bss[(lrow+64)*SPITCH+lcol+2] = tf32r(b1.z - b);
        b = tf32r(b1.w); bsb[(lrow+64)*SPITCH+lcol+3] = b; bss[(lrow+64)*SPITCH+lcol+3] = tf32r(b1.w - b);
    };

    fetch(0);
    asm volatile("cp.async.wait_group 0;\n");
    split_store(0);
    __syncthreads();

    int ntiles = K / TBK;
    for (int t = 0; t < ntiles; t++) {
        bool more = (t + 1 < ntiles);
        if (more) fetch((t + 1) * TBK);

        #pragma unroll
        for (int ks = 0; ks < 2; ks++) {
            int k0 = ks * 8;
            unsigned afb[4][4], afs[4][4], bfb[4][2], bfs[4][2];
            #pragma unroll
            for (int mi = 0; mi < 4; mi++) {
                int m0 = warp_m + mi * 16;
                afb[mi][0] = __float_as_uint(asb[(m0 + qr) * SPITCH + k0 + qc]);
                afb[mi][1] = __float_as_uint(asb[(m0 + qr + 8) * SPITCH + k0 + qc]);
                afb[mi][2] = __float_as_uint(asb[(m0 + qr) * SPITCH + k0 + qc + 4]);
                afb[mi][3] = __float_as_uint(asb[(m0 + qr + 8) * SPITCH + k0 + qc + 4]);
                afs[mi][0] = __float_as_uint(ass[(m0 + qr) * SPITCH + k0 + qc]);
                afs[mi][1] = __float_as_uint(ass[(m0 + qr + 8) * SPITCH + k0 + qc]);
                afs[mi][2] = __float_as_uint(ass[(m0 + qr) * SPITCH + k0 + qc + 4]);
                afs[mi][3] = __float_as_uint(ass[(m0 + qr + 8) * SPITCH + k0 + qc + 4]);
            }
            #pragma unroll
            for (int ni = 0; ni < 4; ni++) {
                int n0 = warp_n + ni * 8;
                bfb[ni][0] = __float_as_uint(bsb[(n0 + qr) * SPITCH + k0 + qc]);
                bfb[ni][1] = __float_as_uint(bsb[(n0 + qr) * SPITCH + k0 + qc + 4]);
                bfs[ni][0] = __float_as_uint(bss[(n0 + qr) * SPITCH + k0 + qc]);
                bfs[ni][1] = __float_as_uint(bss[(n0 + qr) * SPITCH + k0 + qc + 4]);
            }
            #pragma unroll
            for (int mi = 0; mi < 4; mi++)
                #pragma unroll
                for (int ni = 0; ni < 4; ni++) {
                    mma_tf32(acc[mi][ni], afs[mi], bfb[ni]);
                    mma_tf32(acc[mi][ni], afb[mi], bfs[ni]);
                    mma_tf32(acc[mi][ni], afb[mi], bfb[ni]);
                }
        }

        if (more) {
            asm volatile("cp.async.wait_group 0;\n");
            __syncthreads();
            split_store((t + 1) * TBK);
            __syncthreads();
        }
    }

    #pragma unroll
    for (int mi = 0; mi < 4; mi++) {
        #pragma unroll
        for (int ni = 0; ni < 4; ni++) {
            int r = row0 + warp_m + mi * 16 + qr;
            int cc = col0 + warp_n + ni * 8 + qc * 2;
            float2 v0 = {acc[mi][ni][0], acc[mi][ni][1]};
            float2 v1 = {acc[mi][ni][2], acc[mi][ni][3]};
            *(float2*)&C[(size_t)r * N + cc] = v0;
            *(float2*)&C[(size_t)(r + 8) * N + cc] = v1;
        }
    }
}

// --------------------------- bf16x3 GEMM (critical) --------------------------
// C[M,N] = A[M,K]*W[N,K]^T, fp32-class via bf16 split:
//   acc += As*Bb + Ab*Bs + Ab*Bb  (m16n8k16, K=32 tiles -> half the syncs).
#define BTBK 32
#define BPITCH 20                         // words/row: 16 bf16x2 pairs + 4 pad
#define BPLANE (128 * BPITCH)
#define BRAWP 36                          // raw floats/row: 32 + 4 pad
#define BRAWSZ (128 * BRAWP)
#define G3B_SMEM ((4 * BPLANE) * 4 + (2 * BRAWSZ) * 4)   // 40960 + 36864 = 77824

__global__ void __launch_bounds__(256, 2) gemm3xbf16_kernel(
    const float* __restrict__ A, const float* __restrict__ W,
    float* __restrict__ C, int M, int N, int K)
{
    extern __shared__ float sm[];
    unsigned* Abig = (unsigned*)sm;
    unsigned* Asml = Abig + BPLANE;
    unsigned* Bbig = Asml + BPLANE;
    unsigned* Bsml = Bbig + BPLANE;
    float* rawA = (float*)(Bsml + BPLANE);
    float* rawB = rawA + BRAWSZ;

    int tid = threadIdx.x;
    int lane = tid & 31, wid = tid >> 5;
    int warp_m = (wid >> 2) * 64, warp_n = (wid & 3) * 32;
    int qr = lane >> 2, qc = lane & 3;
    int row0 = blockIdx.y * 128, col0 = blockIdx.x * 128;

    // fetch/split mapping: thread = (row 0..127, half 0/1 of 16 floats)
    int frow = tid >> 1;
    int fcol = (tid & 1) * 16;
    int wbase = fcol >> 1;                   // word base in plane (0 or 8)

    const float* ApR = A + (size_t)(row0 + frow) * K + fcol;
    const float* WpR = W + (size_t)(col0 + frow) * K + fcol;

    uint32_t rA = (uint32_t)__cvta_generic_to_shared(rawA + frow * BRAWP + fcol);
    uint32_t rB = (uint32_t)__cvta_generic_to_shared(rawB + frow * BRAWP + fcol);

    float acc[4][4][4];
    #pragma unroll
    for (int i = 0; i < 4; i++)
        #pragma unroll
        for (int j = 0; j < 4; j++)
            #pragma unroll
            for (int r = 0; r < 4; r++) acc[i][j][r] = 0.f;

    auto fetch = [&](int kk) {
        #pragma unroll
        for (int j = 0; j < 4; j++) {
            cp_async16(rA + j * 16, ApR + kk + j * 4);
            cp_async16(rB + j * 16, WpR + kk + j * 4);
        }
        asm volatile("cp.async.commit_group;\n");
    };
    auto split_store = [&]() {
        #pragma unroll
        for (int j = 0; j < 4; j++) {
            float4 av = *(const float4*)(rawA + frow * BRAWP + fcol + j * 4);
            float4 bv = *(const float4*)(rawB + frow * BRAWP + fcol + j * 4);
            unsigned bg0, sl0, bg1, sl1;
            bfsplit2(av.x, av.y, bg0, sl0);
            bfsplit2(av.z, av.w, bg1, sl1);
            *(uint2*)&Abig[frow * BPITCH + wbase + j * 2] = make_uint2(bg0, bg1);
            *(uint2*)&Asml[frow * BPITCH + wbase + j * 2] = make_uint2(sl0, sl1);
            bfsplit2(bv.x, bv.y, bg0, sl0);
            bfsplit2(bv.z, bv.w, bg1, sl1);
            *(uint2*)&Bbig[frow * BPITCH + wbase + j * 2] = make_uint2(bg0, bg1);
            *(uint2*)&Bsml[frow * BPITCH + wbase + j * 2] = make_uint2(sl0, sl1);
        }
    };

    fetch(0);
    asm volatile("cp.async.wait_group 0;\n");
    split_store();
    __syncthreads();

    int ntiles = K / BTBK;
    for (int t = 0; t < ntiles; t++) {
        bool more = (t + 1 < ntiles);
        if (more) fetch((t + 1) * BTBK);

        #pragma unroll
        for (int ks = 0; ks < 2; ks++) {
            int k0w = ks * 8;                // word offset of K=16 slice
            unsigned afb[4][4], afs[4][4], bfb[4][2], bfs[4][2];
            #pragma unroll
            for (int mi = 0; mi < 4; mi++) {
                int m0 = warp_m + mi * 16;
                afb[mi][0] = Abig[(m0 + qr) * BPITCH + k0w + qc];
                afb[mi][1] = Abig[(m0 + qr + 8) * BPITCH + k0w + qc];
                afb[mi][2] = Abig[(m0 + qr) * BPITCH + k0w + qc + 4];
                afb[mi][3] = Abig[(m0 + qr + 8) * BPITCH + k0w + qc + 4];
                afs[mi][0] = Asml[(m0 + qr) * BPITCH + k0w + qc];
                afs[mi][1] = Asml[(m0 + qr + 8) * BPITCH + k0w + qc];
                afs[mi][2] = Asml[(m0 + qr) * BPITCH + k0w + qc + 4];
                afs[mi][3] = Asml[(m0 + qr + 8) * BPITCH + k0w + qc + 4];
            }
            #pragma unroll
            for (int ni = 0; ni < 4; ni++) {
                int n0 = warp_n + ni * 8;
                bfb[ni][0] = Bbig[(n0 + qr) * BPITCH + k0w + qc];
                bfb[ni][1] = Bbig[(n0 + qr) * BPITCH + k0w + qc + 4];
                bfs[ni][0] = Bsml[(n0 + qr) * BPITCH + k0w + qc];
                bfs[ni][1] = Bsml[(n0 + qr) * BPITCH + k0w + qc + 4];
            }
            #pragma unroll
            for (int mi = 0; mi < 4; mi++)
                #pragma unroll
                for (int ni = 0; ni < 4; ni++) {
                    mma_bf16(acc[mi][ni], afs[mi], bfb[ni]);  // As*Bb
                    mma_bf16(acc[mi][ni], afb[mi], bfs[ni]);  // Ab*Bs
                    mma_bf16(acc[mi][ni], afb[mi], bfb[ni]);  // Ab*Bb
                }
        }

        if (more) {
            asm volatile("cp.async.wait_group 0;\n");
            __syncthreads();
            split_store();
            __syncthreads();
        }
    }

    #pragma unroll
    for (int mi = 0; mi < 4; mi++) {
        #pragma unroll
        for (int ni = 0; ni < 4; ni++) {
            int r = row0 + warp_m + mi * 16 + qr;
            int cc = col0 + warp_n + ni * 8 + qc * 2;
            float2 v0 = {acc[mi][ni][0], acc[mi][ni][1]};
            float2 v1 = {acc[mi][ni][2], acc[mi][ni][3]};
            *(float2*)&C[(size_t)r * N + cc] = v0;
            *(float2*)&C[(size_t)(r + 8) * N + cc] = v1;
        }
    }
}

// ------------------------------- CPL ----------------------------------------
__global__ void __launch_bounds__(1024) cpl_kernel(const float* __restrict__ bmax,
                                                   const int* __restrict__ bidx,
                                                   const float* __restrict__ s3,
                                                   const float* __restrict__ h3,
                                                   int* __restrict__ idx_out) {
    __shared__ float maxv[1024];
    __shared__ int   amax[1024];
    __shared__ float score[1024];
    __shared__ float key[1024];
    __shared__ int   packed[1024];

    int b = blockIdx.x;
    int c = threadIdx.x;

    {
        float act = fmaxf(bmax[b * 1024 + c] * s3[c] + h3[c], 0.f);
        maxv[c] = act;
        amax[c] = (act > 0.f) ? bidx[b * 1024 + c] : 0;
    }
    __syncthreads();

    int n = threadIdx.x;
    float sc = 0.f;
    for (int c2 = 0; c2 < 1024; c2++)
        if (amax[c2] == n) sc += maxv[c2];
    score[n] = sc;
    key[n] = (-sc) + CPL_EPS * (float)n;
    int m = __syncthreads_count(sc > 0.f);

    {
        bool any = (m == 0);
        bool mine = any || (score[n] > 0.f);
        if (mine) {
            float kn = key[n];
            int r = 0;
            for (int j = 0; j < 1024; j++) {
                bool sel = any || (score[j] > 0.f);
                if (sel) {
                    float kj = key[j];
                    if (kj < kn || (kj == kn && j < n)) r++;
                }
            }
            packed[r] = n;
        }
    }
    __syncthreads();

    if (threadIdx.x < CPLK) {
        int k = threadIdx.x;
        float mf = (m > 0) ? (float)m : (float)NPTS;
        int pos;
        if (mf >= (float)CPLK) {
            pos = k;
        } else {
            float lin = (float)k * (mf - 1.0f) / (float)(CPLK - 1);
            int p = (int)rintf(lin);
            int hi = (int)(mf - 1.0f);
            p = max(0, min(p, hi));
            pos = p;
        }
        idx_out[b * CPLK + k] = packed[pos];
    }
}

// ------------------------------ gather --------------------------------------
__global__ void __launch_bounds__(256) gather_kernel(const float* __restrict__ Z3,
                                                     const int* __restrict__ idx,
                                                     const float* __restrict__ s3,
                                                     const float* __restrict__ h3,
                                                     float* __restrict__ CR) {
    int i = blockIdx.x;
    int b = i >> 8;
    int src = idx[i];
    const float* p = Z3 + ((size_t)(b * NPTS + src) << 10);
    float* o = CR + ((size_t)i << 10);
    for (int c = threadIdx.x; c < 1024; c += 256)
        o[c] = fmaxf(p[c] * s3[c] + h3[c], 0.f);
}

// ------------------------------ max-pool ------------------------------------
__global__ void __launch_bounds__(256) maxpool_kernel(const float* __restrict__ ZC,
                                                      const float* __restrict__ sc,
                                                      const float* __restrict__ hc,
                                                      float* __restrict__ GF) {
    int b = blockIdx.x;
    int c = blockIdx.y * 256 + threadIdx.x;
    float s = sc[c], h = hc[c];
    const float* p = ZC + ((size_t)(b * CPLK) << 10) + c;
    float m = 0.f;
    for (int k = 0; k < CPLK; k += 4) {
        float v0 = p[(size_t)(k + 0) << 10];
        float v1 = p[(size_t)(k + 1) << 10];
        float v2 = p[(size_t)(k + 2) << 10];
        float v3 = p[(size_t)(k + 3) << 10];
        m = fmaxf(m, fmaxf(v0 * s + h, 0.f));
        m = fmaxf(m, fmaxf(v1 * s + h, 0.f));
        m = fmaxf(m, fmaxf(v2 * s + h, 0.f));
        m = fmaxf(m, fmaxf(v3 * s + h, 0.f));
    }
    GF[b * 1024 + c] = m;
}

// ------------------------------ FC (warp per output) ------------------------
__global__ void __launch_bounds__(256) fc_kernel(const float* __restrict__ Ain,
                                                 const float* __restrict__ W,
                                                 const float* __restrict__ bias,
                                                 const float* __restrict__ s,
                                                 const float* __restrict__ h,
                                                 float* __restrict__ out,
                                                 int B, int O, int Kin, int useAct) {
    int warp = (blockIdx.x * blockDim.x + threadIdx.x) >> 5;
    int lane = threadIdx.x & 31;
    if (warp >= B * O) return;
    int b = warp / O, o = warp - b * O;
    const float* a = Ain + (size_t)b * Kin;
    const float* w = W + (size_t)o * Kin;
    float acc = 0.f;
    for (int k = lane; k < Kin; k += 32) {
        float v = a[k];
        if (useAct) v = fmaxf(v * s[k] + h[k], 0.f);
        acc += v * w[k];
    }
    #pragma unroll
    for (int off = 16; off; off >>= 1)
        acc += __shfl_down_sync(0xffffffffu, acc, off);
    if (lane == 0) out[warp] = acc + bias[o];
}

// ------------------------------- driver --------------------------------------
extern "C" void kernel_launch(void* const* d_in, const int* in_sizes, int n_in,
                              void* d_out, int out_size) {
    const float* x     = (const float*)d_in[0];
    const float* W1    = (const float*)d_in[1];
    const float* g1    = (const float*)d_in[2];
    const float* b1    = (const float*)d_in[3];
    const float* W2    = (const float*)d_in[4];
    const float* g2    = (const float*)d_in[5];
    const float* b2    = (const float*)d_in[6];
    const float* W3    = (const float*)d_in[7];
    const float* g3    = (const float*)d_in[8];
    const float* b3    = (const float*)d_in[9];
    const float* Wc    = (const float*)d_in[10];
    const float* gc    = (const float*)d_in[11];
    const float* bc    = (const float*)d_in[12];
    const float* fc1w  = (const float*)d_in[13];
    const float* fc1b  = (const float*)d_in[14];
    const float* bn1g  = (const float*)d_in[15];
    const float* bn1b  = (const float*)d_in[16];
    const float* fc2w  = (const float*)d_in[17];
    const float* fc2b  = (const float*)d_in[18];
    const float* bn2g  = (const float*)d_in[19];
    const float* bn2b  = (const float*)d_in[20];
    const float* fc3w  = (const float*)d_in[21];
    const float* fc3b  = (const float*)d_in[22];
    float* out = (float*)d_out;

    float *Z1, *Z2, *Z3, *CR, *ZC, *PS, *PQ;
    float *S1, *H1, *S2, *H2, *S3, *H3, *SC, *HC, *SF1, *HF1, *SF2, *HF2;
    float *GF, *O1, *O2, *BMAX;
    int *IDX, *BIDX;
    cudaGetSymbolAddress((void**)&Z1, g_Z1);
    cudaGetSymbolAddress((void**)&Z2, g_Z2);
    cudaGetSymbolAddress((void**)&Z3, g_Z3);
    cudaGetSymbolAddress((void**)&CR, g_CR);
    cudaGetSymbolAddress((void**)&ZC, g_ZC);
    cudaGetSymbolAddress((void**)&PS, g_PS);
    cudaGetSymbolAddress((void**)&PQ, g_PQ);
    cudaGetSymbolAddress((void**)&S1, g_S1);  cudaGetSymbolAddress((void**)&H1, g_H1);
    cudaGetSymbolAddress((void**)&S2, g_S2);  cudaGetSymbolAddress((void**)&H2, g_H2);
    cudaGetSymbolAddress((void**)&S3, g_S3);  cudaGetSymbolAddress((void**)&H3, g_H3);
    cudaGetSymbolAddress((void**)&SC, g_SC);  cudaGetSymbolAddress((void**)&HC, g_HC);
    cudaGetSymbolAddress((void**)&SF1, g_SF1); cudaGetSymbolAddress((void**)&HF1, g_HF1);
    cudaGetSymbolAddress((void**)&SF2, g_SF2); cudaGetSymbolAddress((void**)&HF2, g_HF2);
    cudaGetSymbolAddress((void**)&GF, g_GF);
    cudaGetSymbolAddress((void**)&O1, g_O1);
    cudaGetSymbolAddress((void**)&O2, g_O2);
    cudaGetSymbolAddress((void**)&IDX, g_IDX);
    cudaGetSymbolAddress((void**)&BMAX, g_BMAX);
    cudaGetSymbolAddress((void**)&BIDX, g_BIDX);

    static bool attr_set = false;
    if (!attr_set) {
        cudaFuncSetAttribute(gemm3x_kernel<true>,
                             cudaFuncAttributeMaxDynamicSharedMemorySize, G3X_SMEM);
        cudaFuncSetAttribute(gemm3xbf16_kernel,
                             cudaFuncAttributeMaxDynamicSharedMemorySize, G3B_SMEM);
        attr_set = true;
    }

    dim3 st1b(32, 8);

    // layer 1: 3 -> 64
    l1_kernel<<<MROWS / 4, 256>>>(x, W1, Z1);
    colstats1<<<dim3(64 / 32, 64), st1b>>>(Z1, MROWS, 64, PS, PQ);
    colstats2<<<1, 256>>>(PS, PQ, MROWS, 64, g1, b1, S1, H1);

    // layer 2: 64 -> 128 (fp32, act fused on A load)
    sgemm_kernel<true><<<dim3(1, MROWS / 128), 256>>>(Z1, W2, S1, H1, Z2, MROWS, 128, 64);
    colstats1<<<dim3(128 / 32, 64), st1b>>>(Z2, MROWS, 128, PS, PQ);
    colstats2<<<1, 256>>>(PS, PQ, MROWS, 128, g2, b2, S2, H2);

    // layer 3: 128 -> 1024 (3xTF32 + cp.async, act fused at split)
    gemm3x_kernel<true><<<dim3(1024 / 128, MROWS / 128), 256, G3X_SMEM>>>(
        Z2, W3, S2, H2, Z3, MROWS, 1024, 128);
    colstats1_cpl<<<dim3(1024 / 32, 64), st1b>>>(Z3, PS, PQ, BMAX, BIDX);
    colstats2<<<4, 256>>>(PS, PQ, MROWS, 1024, g3, b3, S3, H3);

    // CPL index selection + gather (activation fused)
    cpl_kernel<<<BATCH, 1024>>>(BMAX, BIDX, S3, H3, IDX);
    gather_kernel<<<MCRIT, 256>>>(Z3, IDX, S3, H3, CR);

    // critical GEMM (bf16x3, m16n8k16, K=32 tiles): 1024 -> 1024
    gemm3xbf16_kernel<<<dim3(1024 / 128, MCRIT / 128), 256, G3B_SMEM>>>(
        CR, Wc, ZC, MCRIT, 1024, 1024);
    colstats1<<<dim3(1024 / 32, 64), st1b>>>(ZC, MCRIT, 1024, PS, PQ);
    colstats2<<<4, 256>>>(PS, PQ, MCRIT, 1024, gc, bc, SC, HC);

    // global max-pool over K (act fused)
    maxpool_kernel<<<dim3(BATCH, 4), 256>>>(ZC, SC, HC, GF);

    // fc1: 1024 -> 512
    fc_kernel<<<(BATCH * 512) / 8, 256>>>(GF, fc1w, fc1b, nullptr, nullptr, O1, BATCH, 512, 1024, 0);
    colstats_small<<<2, 256>>>(O1, BATCH, 512, bn1g, bn1b, SF1, HF1);

    // fc2: 512 -> 256 (act fused)
    fc_kernel<<<(BATCH * 256) / 8, 256>>>(O1, fc2w, fc2b, SF1, HF1, O2, BATCH, 256, 512, 1);
    colstats_small<<<1, 256>>>(O2, BATCH, 256, bn2g, bn2b, SF2, HF2);

    // fc3: 256 -> 40 -> d_out (act fused)
    fc_kernel<<<(BATCH * NCLS + 7) / 8, 256>>>(O2, fc3w, fc3b, SF2, HF2, out, BATCH, NCLS, 256, 1);
}

// round 10
// speedup vs baseline: 1.0377x; 1.0377x over previous
#include <cuda_runtime.h>
#include <cuda_bf16.h>
#include <cstdint>
#include <cstddef>

// ---------------------------------------------------------------------------
// SimplePointNetCPL — layer3 via 3xTF32 (feeds argmax, flip-safe);
// critical GEMM via bf16x3 m16n8k16, TBK=16, DOUBLE-BUFFERED planes
// (1 barrier per k-tile, split overlaps compute skew).
// ---------------------------------------------------------------------------

#define BATCH     64
#define NPTS      1024
#define CPLK      256
#define NCLS      40
#define BN_EPS    1e-5f
#define CPL_EPS   1e-7f

#define MROWS     (BATCH * NPTS)    // 65536
#define MCRIT     (BATCH * CPLK)    // 16384

// ------------------------------- scratch -----------------------------------
__device__ float g_Z1[MROWS * 64];
__device__ float g_Z2[MROWS * 128];
__device__ float g_Z3[(size_t)MROWS * 1024];
__device__ float g_CR[(size_t)MCRIT * 1024];
__device__ float g_ZC[(size_t)MCRIT * 1024];
__device__ float g_PS[64 * 1024];
__device__ float g_PQ[64 * 1024];
__device__ float g_S1[64],  g_H1[64];
__device__ float g_S2[128], g_H2[128];
__device__ float g_S3[1024], g_H3[1024];
__device__ float g_SC[1024], g_HC[1024];
__device__ float g_SF1[512], g_HF1[512];
__device__ float g_SF2[256], g_HF2[256];
__device__ int   g_IDX[BATCH * CPLK];
__device__ float g_GF[BATCH * 1024];
__device__ float g_O1[BATCH * 512];
__device__ float g_O2[BATCH * 256];
__device__ float g_BMAX[BATCH * 1024];
__device__ int   g_BIDX[BATCH * 1024];

// ------------------------- layer 1 (K=3 micro GEMM) -------------------------
__global__ void __launch_bounds__(256) l1_kernel(const float* __restrict__ x,
                                                 const float* __restrict__ W1,
                                                 float* __restrict__ Z1) {
    __shared__ float w[64 * 3];
    if (threadIdx.x < 192) w[threadIdx.x] = W1[threadIdx.x];
    __syncthreads();
    int r = blockIdx.x * 4 + (threadIdx.x >> 6);
    int c = threadIdx.x & 63;
    float x0 = x[r * 3 + 0], x1 = x[r * 3 + 1], x2 = x[r * 3 + 2];
    Z1[(size_t)r * 64 + c] = x0 * w[c * 3 + 0] + x1 * w[c * 3 + 1] + x2 * w[c * 3 + 2];
}

// --------------------------- column statistics ------------------------------
__global__ void colstats1(const float* __restrict__ Z, int M, int N,
                          float* __restrict__ ps, float* __restrict__ pq) {
    int col = blockIdx.x * 32 + threadIdx.x;
    int chunk = M >> 6;
    int r0 = blockIdx.y * chunk;
    float s = 0.f, q = 0.f;
    for (int r = r0 + threadIdx.y; r < r0 + chunk; r += 8) {
        float v = Z[(size_t)r * N + col];
        s += v; q += v * v;
    }
    __shared__ float ss[8][32], qq[8][32];
    ss[threadIdx.y][threadIdx.x] = s;
    qq[threadIdx.y][threadIdx.x] = q;
    __syncthreads();
    if (threadIdx.y == 0) {
        for (int t = 1; t < 8; t++) { s += ss[t][threadIdx.x]; q += qq[t][threadIdx.x]; }
        ps[blockIdx.y * N + col] = s;
        pq[blockIdx.y * N + col] = q;
    }
}

// Z3 variant: also emits per-(batch,channel) raw max + first-argmax.
__global__ void colstats1_cpl(const float* __restrict__ Z,
                              float* __restrict__ ps, float* __restrict__ pq,
                              float* __restrict__ bmax, int* __restrict__ bidx) {
    int col = blockIdx.x * 32 + threadIdx.x;
    int b = blockIdx.y;
    const float* p = Z + ((size_t)b * NPTS) * 1024 + col;
    float s = 0.f, q = 0.f;
    float mv = -3.4e38f; int mi = 0;
    for (int r = threadIdx.y; r < NPTS; r += 8) {
        float v = p[(size_t)r << 10];
        s += v; q += v * v;
        if (v > mv) { mv = v; mi = r; }
    }
    __shared__ float ss[8][32], qq[8][32], mm[8][32];
    __shared__ int   ii[8][32];
    ss[threadIdx.y][threadIdx.x] = s;
    qq[threadIdx.y][threadIdx.x] = q;
    mm[threadIdx.y][threadIdx.x] = mv;
    ii[threadIdx.y][threadIdx.x] = mi;
    __syncthreads();
    if (threadIdx.y == 0) {
        for (int t = 1; t < 8; t++) {
            s += ss[t][threadIdx.x]; q += qq[t][threadIdx.x];
            float tv = mm[t][threadIdx.x]; int ti = ii[t][threadIdx.x];
            if (tv > mv || (tv == mv && ti < mi)) { mv = tv; mi = ti; }
        }
        ps[b * 1024 + col] = s;
        pq[b * 1024 + col] = q;
        bmax[b * 1024 + col] = mv;
        bidx[b * 1024 + col] = mi;
    }
}

__global__ void colstats2(const float* __restrict__ ps, const float* __restrict__ pq,
                          int M, int N,
                          const float* __restrict__ gam, const float* __restrict__ bet,
                          float* __restrict__ scale, float* __restrict__ shift) {
    int col = blockIdx.x * 256 + threadIdx.x;
    if (col >= N) return;
    float s = 0.f, q = 0.f;
    for (int rb = 0; rb < 64; rb++) { s += ps[rb * N + col]; q += pq[rb * N + col]; }
    float mean = s / (float)M;
    float var  = q / (float)M - mean * mean;
    float sc = gam[col] * rsqrtf(var + BN_EPS);
    scale[col] = sc;
    shift[col] = bet[col] - mean * sc;
}

__global__ void colstats_small(const float* __restrict__ Z, int M, int N,
                               const float* __restrict__ gam, const float* __restrict__ bet,
                               float* __restrict__ scale, float* __restrict__ shift) {
    int col = blockIdx.x * 256 + threadIdx.x;
    if (col >= N) return;
    float s = 0.f, q = 0.f;
    for (int r = 0; r < M; r++) { float v = Z[(size_t)r * N + col]; s += v; q += v * v; }
    float mean = s / (float)M;
    float var  = q / (float)M - mean * mean;
    float sc = gam[col] * rsqrtf(var + BN_EPS);
    scale[col] = sc;
    shift[col] = bet[col] - mean * sc;
}

// ------------------------------- fp32 SGEMM (layer 2) -----------------------
template<bool ACT>
__global__ void __launch_bounds__(256) sgemm_kernel(
    const float* __restrict__ A, const float* __restrict__ W,
    const float* __restrict__ scale, const float* __restrict__ shift,
    float* __restrict__ C, int M, int N, int K)
{
    __shared__ float As[8][128];
    __shared__ float Bs[8][128];
    int tid = threadIdx.x;
    int tx = tid & 15, ty = tid >> 4;
    int row0 = blockIdx.y * 128;
    int col0 = blockIdx.x * 128;

    int lr = tid >> 1;
    int lk = (tid & 1) * 4;

    const float* Aptr = A + (size_t)(row0 + lr) * K + lk;
    const float* Wptr = W + (size_t)(col0 + lr) * K + lk;

    float acc[8][8];
    #pragma unroll
    for (int i = 0; i < 8; i++)
        #pragma unroll
        for (int j = 0; j < 8; j++) acc[i][j] = 0.f;

    for (int kk = 0; kk < K; kk += 8) {
        float4 av = *(const float4*)(Aptr + kk);
        float4 wv = *(const float4*)(Wptr + kk);
        if (ACT) {
            float4 sv = *(const float4*)(scale + kk + lk);
            float4 hv = *(const float4*)(shift + kk + lk);
            av.x = fmaxf(av.x * sv.x + hv.x, 0.f);
            av.y = fmaxf(av.y * sv.y + hv.y, 0.f);
            av.z = fmaxf(av.z * sv.z + hv.z, 0.f);
            av.w = fmaxf(av.w * sv.w + hv.w, 0.f);
        }
        As[lk + 0][lr] = av.x; As[lk + 1][lr] = av.y;
        As[lk + 2][lr] = av.z; As[lk + 3][lr] = av.w;
        Bs[lk + 0][lr] = wv.x; Bs[lk + 1][lr] = wv.y;
        Bs[lk + 2][lr] = wv.z; Bs[lk + 3][lr] = wv.w;
        __syncthreads();
        #pragma unroll
        for (int k = 0; k < 8; k++) {
            float4 a0 = *(const float4*)&As[k][ty * 4];
            float4 a1 = *(const float4*)&As[k][ty * 4 + 64];
            float4 b0 = *(const float4*)&Bs[k][tx * 4];
            float4 b1 = *(const float4*)&Bs[k][tx * 4 + 64];
            float ar[8] = {a0.x, a0.y, a0.z, a0.w, a1.x, a1.y, a1.z, a1.w};
            float br[8] = {b0.x, b0.y, b0.z, b0.w, b1.x, b1.y, b1.z, b1.w};
            #pragma unroll
            for (int i = 0; i < 8; i++)
                #pragma unroll
                for (int j = 0; j < 8; j++)
                    acc[i][j] += ar[i] * br[j];
        }
        __syncthreads();
    }

    #pragma unroll
    for (int i = 0; i < 8; i++) {
        int r = row0 + ty * 4 + ((i < 4) ? i : 64 + (i - 4));
        float4 v0 = {acc[i][0], acc[i][1], acc[i][2], acc[i][3]};
        float4 v1 = {acc[i][4], acc[i][5], acc[i][6], acc[i][7]};
        *(float4*)&C[(size_t)r * N + col0 + tx * 4]      = v0;
        *(float4*)&C[(size_t)r * N + col0 + tx * 4 + 64] = v1;
    }
}

// ---------------------- shared helpers for MMA kernels -----------------------
#define TBK 16
#define SPITCH 20
#define RAWP 20
#define PLANE  (128 * SPITCH)
#define RAWSZ  (128 * RAWP)
#define G3X_SMEM ((4 * PLANE + 2 * RAWSZ) * 4)   // 61440 bytes (tf32 kernel)

__device__ __forceinline__ float tf32r(float x) {
    unsigned u;
    asm("cvt.rna.tf32.f32 %0, %1;" : "=r"(u) : "f"(x));
    return __uint_as_float(u);
}

__device__ __forceinline__ void mma_tf32(float* c, const unsigned* a, const unsigned* b) {
    asm volatile(
        "mma.sync.aligned.m16n8k8.row.col.f32.tf32.tf32.f32 "
        "{%0,%1,%2,%3}, {%4,%5,%6,%7}, {%8,%9}, {%0,%1,%2,%3};\n"
        : "+f"(c[0]), "+f"(c[1]), "+f"(c[2]), "+f"(c[3])
        : "r"(a[0]), "r"(a[1]), "r"(a[2]), "r"(a[3]), "r"(b[0]), "r"(b[1]));
}

__device__ __forceinline__ void mma_bf16(float* c, const unsigned* a, const unsigned* b) {
    asm volatile(
        "mma.sync.aligned.m16n8k16.row.col.f32.bf16.bf16.f32 "
        "{%0,%1,%2,%3}, {%4,%5,%6,%7}, {%8,%9}, {%0,%1,%2,%3};\n"
        : "+f"(c[0]), "+f"(c[1]), "+f"(c[2]), "+f"(c[3])
        : "r"(a[0]), "r"(a[1]), "r"(a[2]), "r"(a[3]), "r"(b[0]), "r"(b[1]));
}

__device__ __forceinline__ void cp_async16(uint32_t dst, const void* src) {
    asm volatile("cp.async.ca.shared.global [%0], [%1], 16;\n" :: "r"(dst), "l"(src));
}

// pack two floats into bf16x2 word (low = first), and its residual word
__device__ __forceinline__ void bfsplit2(float v0, float v1, unsigned& big, unsigned& small) {
    __nv_bfloat16 b0 = __float2bfloat16_rn(v0);
    __nv_bfloat16 b1 = __float2bfloat16_rn(v1);
    __nv_bfloat16 s0 = __float2bfloat16_rn(v0 - __bfloat162float(b0));
    __nv_bfloat16 s1 = __float2bfloat16_rn(v1 - __bfloat162float(b1));
    unsigned ub0 = (unsigned)__bfloat16_as_ushort(b0);
    unsigned ub1 = (unsigned)__bfloat16_as_ushort(b1);
    unsigned us0 = (unsigned)__bfloat16_as_ushort(s0);
    unsigned us1 = (unsigned)__bfloat16_as_ushort(s1);
    big   = ub0 | (ub1 << 16);
    small = us0 | (us1 << 16);
}

// ------------------------------ 3xTF32 GEMM (layer 3) ------------------------
// R6 engine: split-at-store planes + cp.async raw staging.
template<bool ACT>
__global__ void __launch_bounds__(256, 2) gemm3x_kernel(
    const float* __restrict__ A, const float* __restrict__ W,
    const float* __restrict__ scale, const float* __restrict__ shift,
    float* __restrict__ C, int M, int N, int K)
{
    extern __shared__ float sm[];
    float* asb = sm;
    float* ass = sm + PLANE;
    float* bsb = sm + 2 * PLANE;
    float* bss = sm + 3 * PLANE;
    float* rawA = sm + 4 * PLANE;
    float* rawB = rawA + RAWSZ;

    int tid = threadIdx.x;
    int lane = tid & 31, wid = tid >> 5;
    int warp_m = (wid >> 2) * 64, warp_n = (wid & 3) * 32;
    int qr = lane >> 2, qc = lane & 3;
    int row0 = blockIdx.y * 128, col0 = blockIdx.x * 128;

    int lrow = tid >> 2;
    int lcol = (tid & 3) * 4;

    const float* Ap0 = A + (size_t)(row0 + lrow) * K + lcol;
    const float* Ap1 = A + (size_t)(row0 + lrow + 64) * K + lcol;
    const float* Wp0 = W + (size_t)(col0 + lrow) * K + lcol;
    const float* Wp1 = W + (size_t)(col0 + lrow + 64) * K + lcol;

    uint32_t rA0 = (uint32_t)__cvta_generic_to_shared(rawA + lrow * RAWP + lcol);
    uint32_t rA1 = (uint32_t)__cvta_generic_to_shared(rawA + (lrow + 64) * RAWP + lcol);
    uint32_t rB0 = (uint32_t)__cvta_generic_to_shared(rawB + lrow * RAWP + lcol);
    uint32_t rB1 = (uint32_t)__cvta_generic_to_shared(rawB + (lrow + 64) * RAWP + lcol);

    float acc[4][4][4];
    #pragma unroll
    for (int i = 0; i < 4; i++)
        #pragma unroll
        for (int j = 0; j < 4; j++)
            #pragma unroll
            for (int r = 0; r < 4; r++) acc[i][j][r] = 0.f;

    auto fetch = [&](int kk) {
        cp_async16(rA0, Ap0 + kk);
        cp_async16(rA1, Ap1 + kk);
        cp_async16(rB0, Wp0 + kk);
        cp_async16(rB1, Wp1 + kk);
        asm volatile("cp.async.commit_group;\n");
    };
    auto split_store = [&](int kk) {
        float4 a0 = *(const float4*)(rawA + lrow * RAWP + lcol);
        float4 a1 = *(const float4*)(rawA + (lrow + 64) * RAWP + lcol);
        float4 b0 = *(const float4*)(rawB + lrow * RAWP + lcol);
        float4 b1 = *(const float4*)(rawB + (lrow + 64) * RAWP + lcol);
        if (ACT) {
            float4 sv = *(const float4*)(scale + kk + lcol);
            float4 hv = *(const float4*)(shift + kk + lcol);
            a0.x = fmaxf(a0.x * sv.x + hv.x, 0.f);
            a0.y = fmaxf(a0.y * sv.y + hv.y, 0.f);
            a0.z = fmaxf(a0.z * sv.z + hv.z, 0.f);
            a0.w = fmaxf(a0.w * sv.w + hv.w, 0.f);
            a1.x = fmaxf(a1.x * sv.x + hv.x, 0.f);
            a1.y = fmaxf(a1.y * sv.y + hv.y, 0.f);
            a1.z = fmaxf(a1.z * sv.z + hv.z, 0.f);
            a1.w = fmaxf(a1.w * sv.w + hv.w, 0.f);
        }
        float b;
        b = tf32r(a0.x); asb[lrow*SPITCH+lcol+0] = b; ass[lrow*SPITCH+lcol+0] = tf32r(a0.x - b);
        b = tf32r(a0.y); asb[lrow*SPITCH+lcol+1] = b; ass[lrow*SPITCH+lcol+1] = tf32r(a0.y - b);
        b = tf32r(a0.z); asb[lrow*SPITCH+lcol+2] = b; ass[lrow*SPITCH+lcol+2] = tf32r(a0.z - b);
        b = tf32r(a0.w); asb[lrow*SPITCH+lcol+3] = b; ass[lrow*SPITCH+lcol+3] = tf32r(a0.w - b);
        b = tf32r(a1.x); asb[(lrow+64)*SPITCH+lcol+0] = b; ass[(lrow+64)*SPITCH+lcol+0] = tf32r(a1.x - b);
        b = tf32r(a1.y); asb[(lrow+64)*SPITCH+lcol+1] = b; ass[(lrow+64)*SPITCH+lcol+1] = tf32r(a1.y - b);
        b = tf32r(a1.z); asb[(lrow+64)*SPITCH+lcol+2] = b; ass[(lrow+64)*SPITCH+lcol+2] = tf32r(a1.z - b);
        b = tf32r(a1.w); asb[(lrow+64)*SPITCH+lcol+3] = b; ass[(lrow+64)*SPITCH+lcol+3] = tf32r(a1.w - b);
        b = tf32r(b0.x); bsb[lrow*SPITCH+lcol+0] = b; bss[lrow*SPITCH+lcol+0] = tf32r(b0.x - b);
        b = tf32r(b0.y); bsb[lrow*SPITCH+lcol+1] = b; bss[lrow*SPITCH+lcol+1] = tf32r(b0.y - b);
        b = tf32r(b0.z); bsb[lrow*SPITCH+lcol+2] = b; bss[lrow*SPITCH+lcol+2] = tf32r(b0.z - b);
        b = tf32r(b0.w); bsb[lrow*SPITCH+lcol+3] = b; bss[lrow*SPITCH+lcol+3] = tf32r(b0.w - b);
        b = tf32r(b1.x); bsb[(lrow+64)*SPITCH+lcol+0] = b; bss[(lrow+64)*SPITCH+lcol+0] = tf32r(b1.x - b);
        b = tf32r(b1.y); bsb[(lrow+64)*SPITCH+lcol+1] = b; bss[(lrow+64)*SPITCH+lcol+1] = tf32r(b1.y - b);
        b = tf32r(b1.z); bsb[(lrow+64)*SPITCH+lcol+2] = b; bss[(lrow+64)*SPITCH+lcol+2] = tf32r(b1.z - b);
        b = tf32r(b1.w); bsb[(lrow+64)*SPITCH+lcol+3] = b; bss[(lrow+64)*SPITCH+lcol+3] = tf32r(b1.w - b);
    };

    fetch(0);
    asm volatile("cp.async.wait_group 0;\n");
    split_store(0);
    __syncthreads();

    int ntiles = K / TBK;
    for (int t = 0; t < ntiles; t++) {
        bool more = (t + 1 < ntiles);
        if (more) fetch((t + 1) * TBK);

        #pragma unroll
        for (int ks = 0; ks < 2; ks++) {
            int k0 = ks * 8;
            unsigned afb[4][4], afs[4][4], bfb[4][2], bfs[4][2];
            #pragma unroll
            for (int mi = 0; mi < 4; mi++) {
                int m0 = warp_m + mi * 16;
                afb[mi][0] = __float_as_uint(asb[(m0 + qr) * SPITCH + k0 + qc]);
                afb[mi][1] = __float_as_uint(asb[(m0 + qr + 8) * SPITCH + k0 + qc]);
                afb[mi][2] = __float_as_uint(asb[(m0 + qr) * SPITCH + k0 + qc + 4]);
                afb[mi][3] = __float_as_uint(asb[(m0 + qr + 8) * SPITCH + k0 + qc + 4]);
                afs[mi][0] = __float_as_uint(ass[(m0 + qr) * SPITCH + k0 + qc]);
                afs[mi][1] = __float_as_uint(ass[(m0 + qr + 8) * SPITCH + k0 + qc]);
                afs[mi][2] = __float_as_uint(ass[(m0 + qr) * SPITCH + k0 + qc + 4]);
                afs[mi][3] = __float_as_uint(ass[(m0 + qr + 8) * SPITCH + k0 + qc + 4]);
            }
            #pragma unroll
            for (int ni = 0; ni < 4; ni++) {
                int n0 = warp_n + ni * 8;
                bfb[ni][0] = __float_as_uint(bsb[(n0 + qr) * SPITCH + k0 + qc]);
                bfb[ni][1] = __float_as_uint(bsb[(n0 + qr) * SPITCH + k0 + qc + 4]);
                bfs[ni][0] = __float_as_uint(bss[(n0 + qr) * SPITCH + k0 + qc]);
                bfs[ni][1] = __float_as_uint(bss[(n0 + qr) * SPITCH + k0 + qc + 4]);
            }
            #pragma unroll
            for (int mi = 0; mi < 4; mi++)
                #pragma unroll
                for (int ni = 0; ni < 4; ni++) {
                    mma_tf32(acc[mi][ni], afs[mi], bfb[ni]);
                    mma_tf32(acc[mi][ni], afb[mi], bfs[ni]);
                    mma_tf32(acc[mi][ni], afb[mi], bfb[ni]);
                }
        }

        if (more) {
            asm volatile("cp.async.wait_group 0;\n");
            __syncthreads();
            split_store((t + 1) * TBK);
            __syncthreads();
        }
    }

    #pragma unroll
    for (int mi = 0; mi < 4; mi++) {
        #pragma unroll
        for (int ni = 0; ni < 4; ni++) {
            int r = row0 + warp_m + mi * 16 + qr;
            int cc = col0 + warp_n + ni * 8 + qc * 2;
            float2 v0 = {acc[mi][ni][0], acc[mi][ni][1]};
            float2 v1 = {acc[mi][ni][2], acc[mi][ni][3]};
            *(float2*)&C[(size_t)r * N + cc] = v0;
            *(float2*)&C[(size_t)(r + 8) * N + cc] = v1;
        }
    }
}

// --------------------------- bf16x3 GEMM (critical) --------------------------
// C[M,N] = A[M,K]*W[N,K]^T, fp32-class via bf16 split, m16n8k16, TBK=16,
// DOUBLE-BUFFERED planes: split(t+1) targets buf^1 -> only ONE barrier/tile.
#define BPITCH 12
#define BPLANE (128 * BPITCH)               // words per plane
#define G3B_SMEM ((8 * BPLANE) * 4 + (2 * RAWSZ) * 4)   // 49152 + 20480 = 69632

__global__ void __launch_bounds__(256, 2) gemm3xbf16_kernel(
    const float* __restrict__ A, const float* __restrict__ W,
    float* __restrict__ C, int M, int N, int K)
{
    extern __shared__ float sm[];
    unsigned* planes = (unsigned*)sm;               // [2 bufs][4 planes][BPLANE]
    float* rawA = (float*)(planes + 8 * BPLANE);
    float* rawB = rawA + RAWSZ;

    int tid = threadIdx.x;
    int lane = tid & 31, wid = tid >> 5;
    int warp_m = (wid >> 2) * 64, warp_n = (wid & 3) * 32;
    int qr = lane >> 2, qc = lane & 3;
    int row0 = blockIdx.y * 128, col0 = blockIdx.x * 128;

    int lrow = tid >> 2;
    int lcol = (tid & 3) * 4;          // float col within k-tile
    int lpair = lcol >> 1;             // word (pair) index: 0,2,4,6

    const float* Ap0 = A + (size_t)(row0 + lrow) * K + lcol;
    const float* Ap1 = A + (size_t)(row0 + lrow + 64) * K + lcol;
    const float* Wp0 = W + (size_t)(col0 + lrow) * K + lcol;
    const float* Wp1 = W + (size_t)(col0 + lrow + 64) * K + lcol;

    uint32_t rA0 = (uint32_t)__cvta_generic_to_shared(rawA + lrow * RAWP + lcol);
    uint32_t rA1 = (uint32_t)__cvta_generic_to_shared(rawA + (lrow + 64) * RAWP + lcol);
    uint32_t rB0 = (uint32_t)__cvta_generic_to_shared(rawB + lrow * RAWP + lcol);
    uint32_t rB1 = (uint32_t)__cvta_generic_to_shared(rawB + (lrow + 64) * RAWP + lcol);

    float acc[4][4][4];
    #pragma unroll
    for (int i = 0; i < 4; i++)
        #pragma unroll
        for (int j = 0; j < 4; j++)
            #pragma unroll
            for (int r = 0; r < 4; r++) acc[i][j][r] = 0.f;

    auto fetch = [&](int kk) {
        cp_async16(rA0, Ap0 + kk);
        cp_async16(rA1, Ap1 + kk);
        cp_async16(rB0, Wp0 + kk);
        cp_async16(rB1, Wp1 + kk);
        asm volatile("cp.async.commit_group;\n");
    };
    auto split_store = [&](int buf) {
        unsigned* Abig = planes + (size_t)buf * 4 * BPLANE;
        unsigned* Asml = Abig + BPLANE;
        unsigned* Bbig = Asml + BPLANE;
        unsigned* Bsml = Bbig + BPLANE;
        float4 a0 = *(const float4*)(rawA + lrow * RAWP + lcol);
        float4 a1 = *(const float4*)(rawA + (lrow + 64) * RAWP + lcol);
        float4 b0 = *(const float4*)(rawB + lrow * RAWP + lcol);
        float4 b1 = *(const float4*)(rawB + (lrow + 64) * RAWP + lcol);
        unsigned bg, sl;
        bfsplit2(a0.x, a0.y, bg, sl);
        Abig[lrow * BPITCH + lpair] = bg;  Asml[lrow * BPITCH + lpair] = sl;
        bfsplit2(a0.z, a0.w, bg, sl);
        Abig[lrow * BPITCH + lpair + 1] = bg;  Asml[lrow * BPITCH + lpair + 1] = sl;
        bfsplit2(a1.x, a1.y, bg, sl);
        Abig[(lrow + 64) * BPITCH + lpair] = bg;  Asml[(lrow + 64) * BPITCH + lpair] = sl;
        bfsplit2(a1.z, a1.w, bg, sl);
        Abig[(lrow + 64) * BPITCH + lpair + 1] = bg;  Asml[(lrow + 64) * BPITCH + lpair + 1] = sl;
        bfsplit2(b0.x, b0.y, bg, sl);
        Bbig[lrow * BPITCH + lpair] = bg;  Bsml[lrow * BPITCH + lpair] = sl;
        bfsplit2(b0.z, b0.w, bg, sl);
        Bbig[lrow * BPITCH + lpair + 1] = bg;  Bsml[lrow * BPITCH + lpair + 1] = sl;
        bfsplit2(b1.x, b1.y, bg, sl);
        Bbig[(lrow + 64) * BPITCH + lpair] = bg;  Bsml[(lrow + 64) * BPITCH + lpair] = sl;
        bfsplit2(b1.z, b1.w, bg, sl);
        Bbig[(lrow + 64) * BPITCH + lpair + 1] = bg;  Bsml[(lrow + 64) * BPITCH + lpair + 1] = sl;
    };

    fetch(0);
    asm volatile("cp.async.wait_group 0;\n");
    split_store(0);
    __syncthreads();

    int ntiles = K / TBK;
    for (int t = 0; t < ntiles; t++) {
        int buf = t & 1;
        bool more = (t + 1 < ntiles);
        if (more) fetch((t + 1) * TBK);

        const unsigned* Abig = planes + (size_t)buf * 4 * BPLANE;
        const unsigned* Asml = Abig + BPLANE;
        const unsigned* Bbig = Asml + BPLANE;
        const unsigned* Bsml = Bbig + BPLANE;

        // one m16n8k16 slice covers the whole K=16 tile
        unsigned afb[4][4], afs[4][4], bfb[4][2], bfs[4][2];
        #pragma unroll
        for (int mi = 0; mi < 4; mi++) {
            int m0 = warp_m + mi * 16;
            afb[mi][0] = Abig[(m0 + qr) * BPITCH + qc];
            afb[mi][1] = Abig[(m0 + qr + 8) * BPITCH + qc];
            afb[mi][2] = Abig[(m0 + qr) * BPITCH + qc + 4];
            afb[mi][3] = Abig[(m0 + qr + 8) * BPITCH + qc + 4];
            afs[mi][0] = Asml[(m0 + qr) * BPITCH + qc];
            afs[mi][1] = Asml[(m0 + qr + 8) * BPITCH + qc];
            afs[mi][2] = Asml[(m0 + qr) * BPITCH + qc + 4];
            afs[mi][3] = Asml[(m0 + qr + 8) * BPITCH + qc + 4];
        }
        #pragma unroll
        for (int ni = 0; ni < 4; ni++) {
            int n0 = warp_n + ni * 8;
            bfb[ni][0] = Bbig[(n0 + qr) * BPITCH + qc];
            bfb[ni][1] = Bbig[(n0 + qr) * BPITCH + qc + 4];
            bfs[ni][0] = Bsml[(n0 + qr) * BPITCH + qc];
            bfs[ni][1] = Bsml[(n0 + qr) * BPITCH + qc + 4];
        }
        #pragma unroll
        for (int mi = 0; mi < 4; mi++)
            #pragma unroll
            for (int ni = 0; ni < 4; ni++) {
                mma_bf16(acc[mi][ni], afs[mi], bfb[ni]);  // As*Bb
                mma_bf16(acc[mi][ni], afb[mi], bfs[ni]);  // Ab*Bs
                mma_bf16(acc[mi][ni], afb[mi], bfb[ni]);  // Ab*Bb
            }

        if (more) {
            // own cp.async data ready -> split into the OTHER buffer (no
            // read/write conflict with warps still computing on `buf`).
            asm volatile("cp.async.wait_group 0;\n");
            split_store(buf ^ 1);
            __syncthreads();       // planes[buf^1] complete before next tile
        }
    }

    #pragma unroll
    for (int mi = 0; mi < 4; mi++) {
        #pragma unroll
        for (int ni = 0; ni < 4; ni++) {
            int r = row0 + warp_m + mi * 16 + qr;
            int cc = col0 + warp_n + ni * 8 + qc * 2;
            float2 v0 = {acc[mi][ni][0], acc[mi][ni][1]};
            float2 v1 = {acc[mi][ni][2], acc[mi][ni][3]};
            *(float2*)&C[(size_t)r * N + cc] = v0;
            *(float2*)&C[(size_t)(r + 8) * N + cc] = v1;
        }
    }
}

// ------------------------------- CPL ----------------------------------------
__global__ void __launch_bounds__(1024) cpl_kernel(const float* __restrict__ bmax,
                                                   const int* __restrict__ bidx,
                                                   const float* __restrict__ s3,
                                                   const float* __restrict__ h3,
                                                   int* __restrict__ idx_out) {
    __shared__ float maxv[1024];
    __shared__ int   amax[1024];
    __shared__ float score[1024];
    __shared__ float key[1024];
    __shared__ int   packed[1024];

    int b = blockIdx.x;
    int c = threadIdx.x;

    {
        float act = fmaxf(bmax[b * 1024 + c] * s3[c] + h3[c], 0.f);
        maxv[c] = act;
        amax[c] = (act > 0.f) ? bidx[b * 1024 + c] : 0;
    }
    __syncthreads();

    int n = threadIdx.x;
    float sc = 0.f;
    for (int c2 = 0; c2 < 1024; c2++)
        if (amax[c2] == n) sc += maxv[c2];
    score[n] = sc;
    key[n] = (-sc) + CPL_EPS * (float)n;
    int m = __syncthreads_count(sc > 0.f);

    {
        bool any = (m == 0);
        bool mine = any || (score[n] > 0.f);
        if (mine) {
            float kn = key[n];
            int r = 0;
            for (int j = 0; j < 1024; j++) {
                bool sel = any || (score[j] > 0.f);
                if (sel) {
                    float kj = key[j];
                    if (kj < kn || (kj == kn && j < n)) r++;
                }
            }
            packed[r] = n;
        }
    }
    __syncthreads();

    if (threadIdx.x < CPLK) {
        int k = threadIdx.x;
        float mf = (m > 0) ? (float)m : (float)NPTS;
        int pos;
        if (mf >= (float)CPLK) {
            pos = k;
        } else {
            float lin = (float)k * (mf - 1.0f) / (float)(CPLK - 1);
            int p = (int)rintf(lin);
            int hi = (int)(mf - 1.0f);
            p = max(0, min(p, hi));
            pos = p;
        }
        idx_out[b * CPLK + k] = packed[pos];
    }
}

// ------------------------------ gather --------------------------------------
__global__ void __launch_bounds__(256) gather_kernel(const float* __restrict__ Z3,
                                                     const int* __restrict__ idx,
                                                     const float* __restrict__ s3,
                                                     const float* __restrict__ h3,
                                                     float* __restrict__ CR) {
    int i = blockIdx.x;
    int b = i >> 8;
    int src = idx[i];
    const float* p = Z3 + ((size_t)(b * NPTS + src) << 10);
    float* o = CR + ((size_t)i << 10);
    for (int c = threadIdx.x; c < 1024; c += 256)
        o[c] = fmaxf(p[c] * s3[c] + h3[c], 0.f);
}

// ------------------------------ max-pool ------------------------------------
__global__ void __launch_bounds__(256) maxpool_kernel(const float* __restrict__ ZC,
                                                      const float* __restrict__ sc,
                                                      const float* __restrict__ hc,
                                                      float* __restrict__ GF) {
    int b = blockIdx.x;
    int c = blockIdx.y * 256 + threadIdx.x;
    float s = sc[c], h = hc[c];
    const float* p = ZC + ((size_t)(b * CPLK) << 10) + c;
    float m = 0.f;
    for (int k = 0; k < CPLK; k += 4) {
        float v0 = p[(size_t)(k + 0) << 10];
        float v1 = p[(size_t)(k + 1) << 10];
        float v2 = p[(size_t)(k + 2) << 10];
        float v3 = p[(size_t)(k + 3) << 10];
        m = fmaxf(m, fmaxf(v0 * s + h, 0.f));
        m = fmaxf(m, fmaxf(v1 * s + h, 0.f));
        m = fmaxf(m, fmaxf(v2 * s + h, 0.f));
        m = fmaxf(m, fmaxf(v3 * s + h, 0.f));
    }
    GF[b * 1024 + c] = m;
}

// ------------------------------ FC (warp per output) ------------------------
__global__ void __launch_bounds__(256) fc_kernel(const float* __restrict__ Ain,
                                                 const float* __restrict__ W,
                                                 const float* __restrict__ bias,
                                                 const float* __restrict__ s,
                                                 const float* __restrict__ h,
                                                 float* __restrict__ out,
                                                 int B, int O, int Kin, int useAct) {
    int warp = (blockIdx.x * blockDim.x + threadIdx.x) >> 5;
    int lane = threadIdx.x & 31;
    if (warp >= B * O) return;
    int b = warp / O, o = warp - b * O;
    const float* a = Ain + (size_t)b * Kin;
    const float* w = W + (size_t)o * Kin;
    float acc = 0.f;
    for (int k = lane; k < Kin; k += 32) {
        float v = a[k];
        if (useAct) v = fmaxf(v * s[k] + h[k], 0.f);
        acc += v * w[k];
    }
    #pragma unroll
    for (int off = 16; off; off >>= 1)
        acc += __shfl_down_sync(0xffffffffu, acc, off);
    if (lane == 0) out[warp] = acc + bias[o];
}

// ------------------------------- driver --------------------------------------
extern "C" void kernel_launch(void* const* d_in, const int* in_sizes, int n_in,
                              void* d_out, int out_size) {
    const float* x     = (const float*)d_in[0];
    const float* W1    = (const float*)d_in[1];
    const float* g1    = (const float*)d_in[2];
    const float* b1    = (const float*)d_in[3];
    const float* W2    = (const float*)d_in[4];
    const float* g2    = (const float*)d_in[5];
    const float* b2    = (const float*)d_in[6];
    const float* W3    = (const float*)d_in[7];
    const float* g3    = (const float*)d_in[8];
    const float* b3    = (const float*)d_in[9];
    const float* Wc    = (const float*)d_in[10];
    const float* gc    = (const float*)d_in[11];
    const float* bc    = (const float*)d_in[12];
    const float* fc1w  = (const float*)d_in[13];
    const float* fc1b  = (const float*)d_in[14];
    const float* bn1g  = (const float*)d_in[15];
    const float* bn1b  = (const float*)d_in[16];
    const float* fc2w  = (const float*)d_in[17];
    const float* fc2b  = (const float*)d_in[18];
    const float* bn2g  = (const float*)d_in[19];
    const float* bn2b  = (const float*)d_in[20];
    const float* fc3w  = (const float*)d_in[21];
    const float* fc3b  = (const float*)d_in[22];
    float* out = (float*)d_out;

    float *Z1, *Z2, *Z3, *CR, *ZC, *PS, *PQ;
    float *S1, *H1, *S2, *H2, *S3, *H3, *SC, *HC, *SF1, *HF1, *SF2, *HF2;
    float *GF, *O1, *O2, *BMAX;
    int *IDX, *BIDX;
    cudaGetSymbolAddress((void**)&Z1, g_Z1);
    cudaGetSymbolAddress((void**)&Z2, g_Z2);
    cudaGetSymbolAddress((void**)&Z3, g_Z3);
    cudaGetSymbolAddress((void**)&CR, g_CR);
    cudaGetSymbolAddress((void**)&ZC, g_ZC);
    cudaGetSymbolAddress((void**)&PS, g_PS);
    cudaGetSymbolAddress((void**)&PQ, g_PQ);
    cudaGetSymbolAddress((void**)&S1, g_S1);  cudaGetSymbolAddress((void**)&H1, g_H1);
    cudaGetSymbolAddress((void**)&S2, g_S2);  cudaGetSymbolAddress((void**)&H2, g_H2);
    cudaGetSymbolAddress((void**)&S3, g_S3);  cudaGetSymbolAddress((void**)&H3, g_H3);
    cudaGetSymbolAddress((void**)&SC, g_SC);  cudaGetSymbolAddress((void**)&HC, g_HC);
    cudaGetSymbolAddress((void**)&SF1, g_SF1); cudaGetSymbolAddress((void**)&HF1, g_HF1);
    cudaGetSymbolAddress((void**)&SF2, g_SF2); cudaGetSymbolAddress((void**)&HF2, g_HF2);
    cudaGetSymbolAddress((void**)&GF, g_GF);
    cudaGetSymbolAddress((void**)&O1, g_O1);
    cudaGetSymbolAddress((void**)&O2, g_O2);
    cudaGetSymbolAddress((void**)&IDX, g_IDX);
    cudaGetSymbolAddress((void**)&BMAX, g_BMAX);
    cudaGetSymbolAddress((void**)&BIDX, g_BIDX);

    static bool attr_set = false;
    if (!attr_set) {
        cudaFuncSetAttribute(gemm3x_kernel<true>,
                             cudaFuncAttributeMaxDynamicSharedMemorySize, G3X_SMEM);
        cudaFuncSetAttribute(gemm3xbf16_kernel,
                             cudaFuncAttributeMaxDynamicSharedMemorySize, G3B_SMEM);
        attr_set = true;
    }

    dim3 st1b(32, 8);

    // layer 1: 3 -> 64
    l1_kernel<<<MROWS / 4, 256>>>(x, W1, Z1);
    colstats1<<<dim3(64 / 32, 64), st1b>>>(Z1, MROWS, 64, PS, PQ);
    colstats2<<<1, 256>>>(PS, PQ, MROWS, 64, g1, b1, S1, H1);

    // layer 2: 64 -> 128 (fp32, act fused on A load)
    sgemm_kernel<true><<<dim3(1, MROWS / 128), 256>>>(Z1, W2, S1, H1, Z2, MROWS, 128, 64);
    colstats1<<<dim3(128 / 32, 64), st1b>>>(Z2, MROWS, 128, PS, PQ);
    colstats2<<<1, 256>>>(PS, PQ, MROWS, 128, g2, b2, S2, H2);

    // layer 3: 128 -> 1024 (3xTF32 + cp.async, act fused at split)
    gemm3x_kernel<true><<<dim3(1024 / 128, MROWS / 128), 256, G3X_SMEM>>>(
        Z2, W3, S2, H2, Z3, MROWS, 1024, 128);
    colstats1_cpl<<<dim3(1024 / 32, 64), st1b>>>(Z3, PS, PQ, BMAX, BIDX);
    colstats2<<<4, 256>>>(PS, PQ, MROWS, 1024, g3, b3, S3, H3);

    // CPL index selection + gather (activation fused)
    cpl_kernel<<<BATCH, 1024>>>(BMAX, BIDX, S3, H3, IDX);
    gather_kernel<<<MCRIT, 256>>>(Z3, IDX, S3, H3, CR);

    // critical GEMM (bf16x3, m16n8k16, double-buffered planes): 1024 -> 1024
    gemm3xbf16_kernel<<<dim3(1024 / 128, MCRIT / 128), 256, G3B_SMEM>>>(
        CR, Wc, ZC, MCRIT, 1024, 1024);
    colstats1<<<dim3(1024 / 32, 64), st1b>>>(ZC, MCRIT, 1024, PS, PQ);
    colstats2<<<4, 256>>>(PS, PQ, MCRIT, 1024, gc, bc, SC, HC);

    // global max-pool over K (act fused)
    maxpool_kernel<<<dim3(BATCH, 4), 256>>>(ZC, SC, HC, GF);

    // fc1: 1024 -> 512
    fc_kernel<<<(BATCH * 512) / 8, 256>>>(GF, fc1w, fc1b, nullptr, nullptr, O1, BATCH, 512, 1024, 0);
    colstats_small<<<2, 256>>>(O1, BATCH, 512, bn1g, bn1b, SF1, HF1);

    // fc2: 512 -> 256 (act fused)
    fc_kernel<<<(BATCH * 256) / 8, 256>>>(O1, fc2w, fc2b, SF1, HF1, O2, BATCH, 256, 512, 1);
    colstats_small<<<1, 256>>>(O2, BATCH, 256, bn2g, bn2b, SF2, HF2);

    // fc3: 256 -> 40 -> d_out (act fused)
    fc_kernel<<<(BATCH * NCLS + 7) / 8, 256>>>(O2, fc3w, fc3b, SF2, HF2, out, BATCH, NCLS, 256, 1);
}

// round 11
// speedup vs baseline: 1.0771x; 1.0380x over previous
#include <cuda_runtime.h>
#include <cuda_bf16.h>
#include <cstdint>
#include <cstddef>

// ---------------------------------------------------------------------------
// SimplePointNetCPL — layer3 via 3xTF32 (feeds argmax, flip-safe);
// critical GEMM via bf16x3 m16n8k16, double-buffered planes, ldmatrix
// fragment loads (12 ldmatrix vs 48 LDS per warp-tile).
// ---------------------------------------------------------------------------

#define BATCH     64
#define NPTS      1024
#define CPLK      256
#define NCLS      40
#define BN_EPS    1e-5f
#define CPL_EPS   1e-7f

#define MROWS     (BATCH * NPTS)    // 65536
#define MCRIT     (BATCH * CPLK)    // 16384

// ------------------------------- scratch -----------------------------------
__device__ float g_Z1[MROWS * 64];
__device__ float g_Z2[MROWS * 128];
__device__ float g_Z3[(size_t)MROWS * 1024];
__device__ float g_CR[(size_t)MCRIT * 1024];
__device__ float g_ZC[(size_t)MCRIT * 1024];
__device__ float g_PS[64 * 1024];
__device__ float g_PQ[64 * 1024];
__device__ float g_S1[64],  g_H1[64];
__device__ float g_S2[128], g_H2[128];
__device__ float g_S3[1024], g_H3[1024];
__device__ float g_SC[1024], g_HC[1024];
__device__ float g_SF1[512], g_HF1[512];
__device__ float g_SF2[256], g_HF2[256];
__device__ int   g_IDX[BATCH * CPLK];
__device__ float g_GF[BATCH * 1024];
__device__ float g_O1[BATCH * 512];
__device__ float g_O2[BATCH * 256];
__device__ float g_BMAX[BATCH * 1024];
__device__ int   g_BIDX[BATCH * 1024];

// ------------------------- layer 1 (K=3 micro GEMM) -------------------------
__global__ void __launch_bounds__(256) l1_kernel(const float* __restrict__ x,
                                                 const float* __restrict__ W1,
                                                 float* __restrict__ Z1) {
    __shared__ float w[64 * 3];
    if (threadIdx.x < 192) w[threadIdx.x] = W1[threadIdx.x];
    __syncthreads();
    int r = blockIdx.x * 4 + (threadIdx.x >> 6);
    int c = threadIdx.x & 63;
    float x0 = x[r * 3 + 0], x1 = x[r * 3 + 1], x2 = x[r * 3 + 2];
    Z1[(size_t)r * 64 + c] = x0 * w[c * 3 + 0] + x1 * w[c * 3 + 1] + x2 * w[c * 3 + 2];
}

// --------------------------- column statistics ------------------------------
__global__ void colstats1(const float* __restrict__ Z, int M, int N,
                          float* __restrict__ ps, float* __restrict__ pq) {
    int col = blockIdx.x * 32 + threadIdx.x;
    int chunk = M >> 6;
    int r0 = blockIdx.y * chunk;
    float s = 0.f, q = 0.f;
    for (int r = r0 + threadIdx.y; r < r0 + chunk; r += 8) {
        float v = Z[(size_t)r * N + col];
        s += v; q += v * v;
    }
    __shared__ float ss[8][32], qq[8][32];
    ss[threadIdx.y][threadIdx.x] = s;
    qq[threadIdx.y][threadIdx.x] = q;
    __syncthreads();
    if (threadIdx.y == 0) {
        for (int t = 1; t < 8; t++) { s += ss[t][threadIdx.x]; q += qq[t][threadIdx.x]; }
        ps[blockIdx.y * N + col] = s;
        pq[blockIdx.y * N + col] = q;
    }
}

// Z3 variant: also emits per-(batch,channel) raw max + first-argmax.
__global__ void colstats1_cpl(const float* __restrict__ Z,
                              float* __restrict__ ps, float* __restrict__ pq,
                              float* __restrict__ bmax, int* __restrict__ bidx) {
    int col = blockIdx.x * 32 + threadIdx.x;
    int b = blockIdx.y;
    const float* p = Z + ((size_t)b * NPTS) * 1024 + col;
    float s = 0.f, q = 0.f;
    float mv = -3.4e38f; int mi = 0;
    for (int r = threadIdx.y; r < NPTS; r += 8) {
        float v = p[(size_t)r << 10];
        s += v; q += v * v;
        if (v > mv) { mv = v; mi = r; }
    }
    __shared__ float ss[8][32], qq[8][32], mm[8][32];
    __shared__ int   ii[8][32];
    ss[threadIdx.y][threadIdx.x] = s;
    qq[threadIdx.y][threadIdx.x] = q;
    mm[threadIdx.y][threadIdx.x] = mv;
    ii[threadIdx.y][threadIdx.x] = mi;
    __syncthreads();
    if (threadIdx.y == 0) {
        for (int t = 1; t < 8; t++) {
            s += ss[t][threadIdx.x]; q += qq[t][threadIdx.x];
            float tv = mm[t][threadIdx.x]; int ti = ii[t][threadIdx.x];
            if (tv > mv || (tv == mv && ti < mi)) { mv = tv; mi = ti; }
        }
        ps[b * 1024 + col] = s;
        pq[b * 1024 + col] = q;
        bmax[b * 1024 + col] = mv;
        bidx[b * 1024 + col] = mi;
    }
}

__global__ void colstats2(const float* __restrict__ ps, const float* __restrict__ pq,
                          int M, int N,
                          const float* __restrict__ gam, const float* __restrict__ bet,
                          float* __restrict__ scale, float* __restrict__ shift) {
    int col = blockIdx.x * 256 + threadIdx.x;
    if (col >= N) return;
    float s = 0.f, q = 0.f;
    for (int rb = 0; rb < 64; rb++) { s += ps[rb * N + col]; q += pq[rb * N + col]; }
    float mean = s / (float)M;
    float var  = q / (float)M - mean * mean;
    float sc = gam[col] * rsqrtf(var + BN_EPS);
    scale[col] = sc;
    shift[col] = bet[col] - mean * sc;
}

__global__ void colstats_small(const float* __restrict__ Z, int M, int N,
                               const float* __restrict__ gam, const float* __restrict__ bet,
                               float* __restrict__ scale, float* __restrict__ shift) {
    int col = blockIdx.x * 256 + threadIdx.x;
    if (col >= N) return;
    float s = 0.f, q = 0.f;
    for (int r = 0; r < M; r++) { float v = Z[(size_t)r * N + col]; s += v; q += v * v; }
    float mean = s / (float)M;
    float var  = q / (float)M - mean * mean;
    float sc = gam[col] * rsqrtf(var + BN_EPS);
    scale[col] = sc;
    shift[col] = bet[col] - mean * sc;
}

// ------------------------------- fp32 SGEMM (layer 2) -----------------------
template<bool ACT>
__global__ void __launch_bounds__(256) sgemm_kernel(
    const float* __restrict__ A, const float* __restrict__ W,
    const float* __restrict__ scale, const float* __restrict__ shift,
    float* __restrict__ C, int M, int N, int K)
{
    __shared__ float As[8][128];
    __shared__ float Bs[8][128];
    int tid = threadIdx.x;
    int tx = tid & 15, ty = tid >> 4;
    int row0 = blockIdx.y * 128;
    int col0 = blockIdx.x * 128;

    int lr = tid >> 1;
    int lk = (tid & 1) * 4;

    const float* Aptr = A + (size_t)(row0 + lr) * K + lk;
    const float* Wptr = W + (size_t)(col0 + lr) * K + lk;

    float acc[8][8];
    #pragma unroll
    for (int i = 0; i < 8; i++)
        #pragma unroll
        for (int j = 0; j < 8; j++) acc[i][j] = 0.f;

    for (int kk = 0; kk < K; kk += 8) {
        float4 av = *(const float4*)(Aptr + kk);
        float4 wv = *(const float4*)(Wptr + kk);
        if (ACT) {
            float4 sv = *(const float4*)(scale + kk + lk);
            float4 hv = *(const float4*)(shift + kk + lk);
            av.x = fmaxf(av.x * sv.x + hv.x, 0.f);
            av.y = fmaxf(av.y * sv.y + hv.y, 0.f);
            av.z = fmaxf(av.z * sv.z + hv.z, 0.f);
            av.w = fmaxf(av.w * sv.w + hv.w, 0.f);
        }
        As[lk + 0][lr] = av.x; As[lk + 1][lr] = av.y;
        As[lk + 2][lr] = av.z; As[lk + 3][lr] = av.w;
        Bs[lk + 0][lr] = wv.x; Bs[lk + 1][lr] = wv.y;
        Bs[lk + 2][lr] = wv.z; Bs[lk + 3][lr] = wv.w;
        __syncthreads();
        #pragma unroll
        for (int k = 0; k < 8; k++) {
            float4 a0 = *(const float4*)&As[k][ty * 4];
            float4 a1 = *(const float4*)&As[k][ty * 4 + 64];
            float4 b0 = *(const float4*)&Bs[k][tx * 4];
            float4 b1 = *(const float4*)&Bs[k][tx * 4 + 64];
            float ar[8] = {a0.x, a0.y, a0.z, a0.w, a1.x, a1.y, a1.z, a1.w};
            float br[8] = {b0.x, b0.y, b0.z, b0.w, b1.x, b1.y, b1.z, b1.w};
            #pragma unroll
            for (int i = 0; i < 8; i++)
                #pragma unroll
                for (int j = 0; j < 8; j++)
                    acc[i][j] += ar[i] * br[j];
        }
        __syncthreads();
    }

    #pragma unroll
    for (int i = 0; i < 8; i++) {
        int r = row0 + ty * 4 + ((i < 4) ? i : 64 + (i - 4));
        float4 v0 = {acc[i][0], acc[i][1], acc[i][2], acc[i][3]};
        float4 v1 = {acc[i][4], acc[i][5], acc[i][6], acc[i][7]};
        *(float4*)&C[(size_t)r * N + col0 + tx * 4]      = v0;
        *(float4*)&C[(size_t)r * N + col0 + tx * 4 + 64] = v1;
    }
}

// ---------------------- shared helpers for MMA kernels -----------------------
#define TBK 16
#define SPITCH 20
#define RAWP 20
#define PLANE  (128 * SPITCH)
#define RAWSZ  (128 * RAWP)
#define G3X_SMEM ((4 * PLANE + 2 * RAWSZ) * 4)   // 61440 bytes (tf32 kernel)

__device__ __forceinline__ float tf32r(float x) {
    unsigned u;
    asm("cvt.rna.tf32.f32 %0, %1;" : "=r"(u) : "f"(x));
    return __uint_as_float(u);
}

__device__ __forceinline__ void mma_tf32(float* c, const unsigned* a, const unsigned* b) {
    asm volatile(
        "mma.sync.aligned.m16n8k8.row.col.f32.tf32.tf32.f32 "
        "{%0,%1,%2,%3}, {%4,%5,%6,%7}, {%8,%9}, {%0,%1,%2,%3};\n"
        : "+f"(c[0]), "+f"(c[1]), "+f"(c[2]), "+f"(c[3])
        : "r"(a[0]), "r"(a[1]), "r"(a[2]), "r"(a[3]), "r"(b[0]), "r"(b[1]));
}

__device__ __forceinline__ void mma_bf16(float* c, const unsigned* a, const unsigned* b) {
    asm volatile(
        "mma.sync.aligned.m16n8k16.row.col.f32.bf16.bf16.f32 "
        "{%0,%1,%2,%3}, {%4,%5,%6,%7}, {%8,%9}, {%0,%1,%2,%3};\n"
        : "+f"(c[0]), "+f"(c[1]), "+f"(c[2]), "+f"(c[3])
        : "r"(a[0]), "r"(a[1]), "r"(a[2]), "r"(a[3]), "r"(b[0]), "r"(b[1]));
}

__device__ __forceinline__ void cp_async16(uint32_t dst, const void* src) {
    asm volatile("cp.async.ca.shared.global [%0], [%1], 16;\n" :: "r"(dst), "l"(src));
}

__device__ __forceinline__ void ldm_x4(unsigned& r0, unsigned& r1,
                                       unsigned& r2, unsigned& r3, uint32_t addr) {
    asm volatile("ldmatrix.sync.aligned.m8n8.x4.shared.b16 {%0,%1,%2,%3}, [%4];"
        : "=r"(r0), "=r"(r1), "=r"(r2), "=r"(r3) : "r"(addr));
}

// pack two floats into bf16x2 word (low = first), and its residual word
__device__ __forceinline__ void bfsplit2(float v0, float v1, unsigned& big, unsigned& small) {
    __nv_bfloat16 b0 = __float2bfloat16_rn(v0);
    __nv_bfloat16 b1 = __float2bfloat16_rn(v1);
    __nv_bfloat16 s0 = __float2bfloat16_rn(v0 - __bfloat162float(b0));
    __nv_bfloat16 s1 = __float2bfloat16_rn(v1 - __bfloat162float(b1));
    unsigned ub0 = (unsigned)__bfloat16_as_ushort(b0);
    unsigned ub1 = (unsigned)__bfloat16_as_ushort(b1);
    unsigned us0 = (unsigned)__bfloat16_as_ushort(s0);
    unsigned us1 = (unsigned)__bfloat16_as_ushort(s1);
    big   = ub0 | (ub1 << 16);
    small = us0 | (us1 << 16);
}

// ------------------------------ 3xTF32 GEMM (layer 3) ------------------------
// R6 engine: split-at-store planes + cp.async raw staging.
template<bool ACT>
__global__ void __launch_bounds__(256, 2) gemm3x_kernel(
    const float* __restrict__ A, const float* __restrict__ W,
    const float* __restrict__ scale, const float* __restrict__ shift,
    float* __restrict__ C, int M, int N, int K)
{
    extern __shared__ float sm[];
    float* asb = sm;
    float* ass = sm + PLANE;
    float* bsb = sm + 2 * PLANE;
    float* bss = sm + 3 * PLANE;
    float* rawA = sm + 4 * PLANE;
    float* rawB = rawA + RAWSZ;

    int tid = threadIdx.x;
    int lane = tid & 31, wid = tid >> 5;
    int warp_m = (wid >> 2) * 64, warp_n = (wid & 3) * 32;
    int qr = lane >> 2, qc = lane & 3;
    int row0 = blockIdx.y * 128, col0 = blockIdx.x * 128;

    int lrow = tid >> 2;
    int lcol = (tid & 3) * 4;

    const float* Ap0 = A + (size_t)(row0 + lrow) * K + lcol;
    const float* Ap1 = A + (size_t)(row0 + lrow + 64) * K + lcol;
    const float* Wp0 = W + (size_t)(col0 + lrow) * K + lcol;
    const float* Wp1 = W + (size_t)(col0 + lrow + 64) * K + lcol;

    uint32_t rA0 = (uint32_t)__cvta_generic_to_shared(rawA + lrow * RAWP + lcol);
    uint32_t rA1 = (uint32_t)__cvta_generic_to_shared(rawA + (lrow + 64) * RAWP + lcol);
    uint32_t rB0 = (uint32_t)__cvta_generic_to_shared(rawB + lrow * RAWP + lcol);
    uint32_t rB1 = (uint32_t)__cvta_generic_to_shared(rawB + (lrow + 64) * RAWP + lcol);

    float acc[4][4][4];
    #pragma unroll
    for (int i = 0; i < 4; i++)
        #pragma unroll
        for (int j = 0; j < 4; j++)
            #pragma unroll
            for (int r = 0; r < 4; r++) acc[i][j][r] = 0.f;

    auto fetch = [&](int kk) {
        cp_async16(rA0, Ap0 + kk);
        cp_async16(rA1, Ap1 + kk);
        cp_async16(rB0, Wp0 + kk);
        cp_async16(rB1, Wp1 + kk);
        asm volatile("cp.async.commit_group;\n");
    };
    auto split_store = [&](int kk) {
        float4 a0 = *(const float4*)(rawA + lrow * RAWP + lcol);
        float4 a1 = *(const float4*)(rawA + (lrow + 64) * RAWP + lcol);
        float4 b0 = *(const float4*)(rawB + lrow * RAWP + lcol);
        float4 b1 = *(const float4*)(rawB + (lrow + 64) * RAWP + lcol);
        if (ACT) {
            float4 sv = *(const float4*)(scale + kk + lcol);
            float4 hv = *(const float4*)(shift + kk + lcol);
            a0.x = fmaxf(a0.x * sv.x + hv.x, 0.f);
            a0.y = fmaxf(a0.y * sv.y + hv.y, 0.f);
            a0.z = fmaxf(a0.z * sv.z + hv.z, 0.f);
            a0.w = fmaxf(a0.w * sv.w + hv.w, 0.f);
            a1.x = fmaxf(a1.x * sv.x + hv.x, 0.f);
            a1.y = fmaxf(a1.y * sv.y + hv.y, 0.f);
            a1.z = fmaxf(a1.z * sv.z + hv.z, 0.f);
            a1.w = fmaxf(a1.w * sv.w + hv.w, 0.f);
        }
        float b;
        b = tf32r(a0.x); asb[lrow*SPITCH+lcol+0] = b; ass[lrow*SPITCH+lcol+0] = tf32r(a0.x - b);
        b = tf32r(a0.y); asb[lrow*SPITCH+lcol+1] = b; ass[lrow*SPITCH+lcol+1] = tf32r(a0.y - b);
        b = tf32r(a0.z); asb[lrow*SPITCH+lcol+2] = b; ass[lrow*SPITCH+lcol+2] = tf32r(a0.z - b);
        b = tf32r(a0.w); asb[lrow*SPITCH+lcol+3] = b; ass[lrow*SPITCH+lcol+3] = tf32r(a0.w - b);
        b = tf32r(a1.x); asb[(lrow+64)*SPITCH+lcol+0] = b; ass[(lrow+64)*SPITCH+lcol+0] = tf32r(a1.x - b);
        b = tf32r(a1.y); asb[(lrow+64)*SPITCH+lcol+1] = b; ass[(lrow+64)*SPITCH+lcol+1] = tf32r(a1.y - b);
        b = tf32r(a1.z); asb[(lrow+64)*SPITCH+lcol+2] = b; ass[(lrow+64)*SPITCH+lcol+2] = tf32r(a1.z - b);
        b = tf32r(a1.w); asb[(lrow+64)*SPITCH+lcol+3] = b; ass[(lrow+64)*SPITCH+lcol+3] = tf32r(a1.w - b);
        b = tf32r(b0.x); bsb[lrow*SPITCH+lcol+0] = b; bss[lrow*SPITCH+lcol+0] = tf32r(b0.x - b);
        b = tf32r(b0.y); bsb[lrow*SPITCH+lcol+1] = b; bss[lrow*SPITCH+lcol+1] = tf32r(b0.y - b);
        b = tf32r(b0.z); bsb[lrow*SPITCH+lcol+2] = b; bss[lrow*SPITCH+lcol+2] = tf32r(b0.z - b);
        b = tf32r(b0.w); bsb[lrow*SPITCH+lcol+3] = b; bss[lrow*SPITCH+lcol+3] = tf32r(b0.w - b);
        b = tf32r(b1.x); bsb[(lrow+64)*SPITCH+lcol+0] = b; bss[(lrow+64)*SPITCH+lcol+0] = tf32r(b1.x - b);
        b = tf32r(b1.y); bsb[(lrow+64)*SPITCH+lcol+1] = b; bss[(lrow+64)*SPITCH+lcol+1] = tf32r(b1.y - b);
        b = tf32r(b1.z); bsb[(lrow+64)*SPITCH+lcol+2] = b; bss[(lrow+64)*SPITCH+lcol+2] = tf32r(b1.z - b);
        b = tf32r(b1.w); bsb[(lrow+64)*SPITCH+lcol+3] = b; bss[(lrow+64)*SPITCH+lcol+3] = tf32r(b1.w - b);
    };

    fetch(0);
    asm volatile("cp.async.wait_group 0;\n");
    split_store(0);
    __syncthreads();

    int ntiles = K / TBK;
    for (int t = 0; t < ntiles; t++) {
        bool more = (t + 1 < ntiles);
        if (more) fetch((t + 1) * TBK);

        #pragma unroll
        for (int ks = 0; ks < 2; ks++) {
            int k0 = ks * 8;
            unsigned afb[4][4], afs[4][4], bfb[4][2], bfs[4][2];
            #pragma unroll
            for (int mi = 0; mi < 4; mi++) {
                int m0 = warp_m + mi * 16;
                afb[mi][0] = __float_as_uint(asb[(m0 + qr) * SPITCH + k0 + qc]);
                afb[mi][1] = __float_as_uint(asb[(m0 + qr + 8) * SPITCH + k0 + qc]);
                afb[mi][2] = __float_as_uint(asb[(m0 + qr) * SPITCH + k0 + qc + 4]);
                afb[mi][3] = __float_as_uint(asb[(m0 + qr + 8) * SPITCH + k0 + qc + 4]);
                afs[mi][0] = __float_as_uint(ass[(m0 + qr) * SPITCH + k0 + qc]);
                afs[mi][1] = __float_as_uint(ass[(m0 + qr + 8) * SPITCH + k0 + qc]);
                afs[mi][2] = __float_as_uint(ass[(m0 + qr) * SPITCH + k0 + qc + 4]);
                afs[mi][3] = __float_as_uint(ass[(m0 + qr + 8) * SPITCH + k0 + qc + 4]);
            }
            #pragma unroll
            for (int ni = 0; ni < 4; ni++) {
                int n0 = warp_n + ni * 8;
                bfb[ni][0] = __float_as_uint(bsb[(n0 + qr) * SPITCH + k0 + qc]);
                bfb[ni][1] = __float_as_uint(bsb[(n0 + qr) * SPITCH + k0 + qc + 4]);
                bfs[ni][0] = __float_as_uint(bss[(n0 + qr) * SPITCH + k0 + qc]);
                bfs[ni][1] = __float_as_uint(bss[(n0 + qr) * SPITCH + k0 + qc + 4]);
            }
            #pragma unroll
            for (int mi = 0; mi < 4; mi++)
                #pragma unroll
                for (int ni = 0; ni < 4; ni++) {
                    mma_tf32(acc[mi][ni], afs[mi], bfb[ni]);
                    mma_tf32(acc[mi][ni], afb[mi], bfs[ni]);
                    mma_tf32(acc[mi][ni], afb[mi], bfb[ni]);
                }
        }

        if (more) {
            asm volatile("cp.async.wait_group 0;\n");
            __syncthreads();
            split_store((t + 1) * TBK);
            __syncthreads();
        }
    }

    #pragma unroll
    for (int mi = 0; mi < 4; mi++) {
        #pragma unroll
        for (int ni = 0; ni < 4; ni++) {
            int r = row0 + warp_m + mi * 16 + qr;
            int cc = col0 + warp_n + ni * 8 + qc * 2;
            float2 v0 = {acc[mi][ni][0], acc[mi][ni][1]};
            float2 v1 = {acc[mi][ni][2], acc[mi][ni][3]};
            *(float2*)&C[(size_t)r * N + cc] = v0;
            *(float2*)&C[(size_t)(r + 8) * N + cc] = v1;
        }
    }
}

// --------------------------- bf16x3 GEMM (critical) --------------------------
// C[M,N] = A[M,K]*W[N,K]^T, fp32-class via bf16 split, m16n8k16, TBK=16,
// double-buffered planes + ldmatrix fragment loads.
#define BPITCH 12
#define BPLANE (128 * BPITCH)               // words per plane
#define G3B_SMEM ((8 * BPLANE) * 4 + (2 * RAWSZ) * 4)   // 49152 + 20480 = 69632

__global__ void __launch_bounds__(256, 2) gemm3xbf16_kernel(
    const float* __restrict__ A, const float* __restrict__ W,
    float* __restrict__ C, int M, int N, int K)
{
    extern __shared__ float sm[];
    unsigned* planes = (unsigned*)sm;               // [2 bufs][4 planes][BPLANE]
    float* rawA = (float*)(planes + 8 * BPLANE);
    float* rawB = rawA + RAWSZ;

    int tid = threadIdx.x;
    int lane = tid & 31, wid = tid >> 5;
    int warp_m = (wid >> 2) * 64, warp_n = (wid & 3) * 32;
    int qr = lane >> 2, qc = lane & 3;
    int row0 = blockIdx.y * 128, col0 = blockIdx.x * 128;

    int lrow = tid >> 2;
    int lcol = (tid & 3) * 4;          // float col within k-tile
    int lpair = lcol >> 1;             // word (pair) index: 0,2,4,6

    const float* Ap0 = A + (size_t)(row0 + lrow) * K + lcol;
    const float* Ap1 = A + (size_t)(row0 + lrow + 64) * K + lcol;
    const float* Wp0 = W + (size_t)(col0 + lrow) * K + lcol;
    const float* Wp1 = W + (size_t)(col0 + lrow + 64) * K + lcol;

    uint32_t rA0 = (uint32_t)__cvta_generic_to_shared(rawA + lrow * RAWP + lcol);
    uint32_t rA1 = (uint32_t)__cvta_generic_to_shared(rawA + (lrow + 64) * RAWP + lcol);
    uint32_t rB0 = (uint32_t)__cvta_generic_to_shared(rawB + lrow * RAWP + lcol);
    uint32_t rB1 = (uint32_t)__cvta_generic_to_shared(rawB + (lrow + 64) * RAWP + lcol);

    // ldmatrix lane offsets (in words):
    //  A (x4, tile m16xk16): row = m0 + (lane&15), word = (lane&16)?4:0
    //  B (x4, two n8xk16 tiles): row = n0 + p*16 + ((lane&16)?8:0) + (lane&7),
    //                            word = ((lane>>3)&1)*4
    uint32_t planes_sh = (uint32_t)__cvta_generic_to_shared(planes);
    int a_off = (lane & 15) * BPITCH + ((lane & 16) ? 4 : 0);
    int b_off = (((lane & 16) ? 8 : 0) + (lane & 7)) * BPITCH + (((lane >> 3) & 1) << 2);

    float acc[4][4][4];
    #pragma unroll
    for (int i = 0; i < 4; i++)
        #pragma unroll
        for (int j = 0; j < 4; j++)
            #pragma unroll
            for (int r = 0; r < 4; r++) acc[i][j][r] = 0.f;

    auto fetch = [&](int kk) {
        cp_async16(rA0, Ap0 + kk);
        cp_async16(rA1, Ap1 + kk);
        cp_async16(rB0, Wp0 + kk);
        cp_async16(rB1, Wp1 + kk);
        asm volatile("cp.async.commit_group;\n");
    };
    auto split_store = [&](int buf) {
        unsigned* Abig = planes + (size_t)buf * 4 * BPLANE;
        unsigned* Asml = Abig + BPLANE;
        unsigned* Bbig = Asml + BPLANE;
        unsigned* Bsml = Bbig + BPLANE;
        float4 a0 = *(const float4*)(rawA + lrow * RAWP + lcol);
        float4 a1 = *(const float4*)(rawA + (lrow + 64) * RAWP + lcol);
        float4 b0 = *(const float4*)(rawB + lrow * RAWP + lcol);
        float4 b1 = *(const float4*)(rawB + (lrow + 64) * RAWP + lcol);
        unsigned bg, sl;
        bfsplit2(a0.x, a0.y, bg, sl);
        Abig[lrow * BPITCH + lpair] = bg;  Asml[lrow * BPITCH + lpair] = sl;
        bfsplit2(a0.z, a0.w, bg, sl);
        Abig[lrow * BPITCH + lpair + 1] = bg;  Asml[lrow * BPITCH + lpair + 1] = sl;
        bfsplit2(a1.x, a1.y, bg, sl);
        Abig[(lrow + 64) * BPITCH + lpair] = bg;  Asml[(lrow + 64) * BPITCH + lpair] = sl;
        bfsplit2(a1.z, a1.w, bg, sl);
        Abig[(lrow + 64) * BPITCH + lpair + 1] = bg;  Asml[(lrow + 64) * BPITCH + lpair + 1] = sl;
        bfsplit2(b0.x, b0.y, bg, sl);
        Bbig[lrow * BPITCH + lpair] = bg;  Bsml[lrow * BPITCH + lpair] = sl;
        bfsplit2(b0.z, b0.w, bg, sl);
        Bbig[lrow * BPITCH + lpair + 1] = bg;  Bsml[lrow * BPITCH + lpair + 1] = sl;
        bfsplit2(b1.x, b1.y, bg, sl);
        Bbig[(lrow + 64) * BPITCH + lpair] = bg;  Bsml[(lrow + 64) * BPITCH + lpair] = sl;
        bfsplit2(b1.z, b1.w, bg, sl);
        Bbig[(lrow + 64) * BPITCH + lpair + 1] = bg;  Bsml[(lrow + 64) * BPITCH + lpair + 1] = sl;
    };

    fetch(0);
    asm volatile("cp.async.wait_group 0;\n");
    split_store(0);
    __syncthreads();

    int ntiles = K / TBK;
    for (int t = 0; t < ntiles; t++) {
        int buf = t & 1;
        bool more = (t + 1 < ntiles);
        if (more) fetch((t + 1) * TBK);

        uint32_t base = planes_sh + (uint32_t)buf * 4 * BPLANE * 4;  // bytes
        uint32_t aBigBase = base;
        uint32_t aSmlBase = base + BPLANE * 4;
        uint32_t bBigBase = base + 2 * BPLANE * 4;
        uint32_t bSmlBase = base + 3 * BPLANE * 4;

        unsigned afb[4][4], afs[4][4], bfb[4][2], bfs[4][2];
        #pragma unroll
        for (int mi = 0; mi < 4; mi++) {
            uint32_t off = (uint32_t)(((warp_m + mi * 16) * BPITCH + a_off) * 4);
            ldm_x4(afb[mi][0], afb[mi][1], afb[mi][2], afb[mi][3], aBigBase + off);
            ldm_x4(afs[mi][0], afs[mi][1], afs[mi][2], afs[mi][3], aSmlBase + off);
        }
        #pragma unroll
        for (int p = 0; p < 2; p++) {
            uint32_t off = (uint32_t)(((warp_n + p * 16) * BPITCH + b_off) * 4);
            ldm_x4(bfb[2*p][0], bfb[2*p][1], bfb[2*p+1][0], bfb[2*p+1][1], bBigBase + off);
            ldm_x4(bfs[2*p][0], bfs[2*p][1], bfs[2*p+1][0], bfs[2*p+1][1], bSmlBase + off);
        }
        #pragma unroll
        for (int mi = 0; mi < 4; mi++)
            #pragma unroll
            for (int ni = 0; ni < 4; ni++) {
                mma_bf16(acc[mi][ni], afs[mi], bfb[ni]);  // As*Bb
                mma_bf16(acc[mi][ni], afb[mi], bfs[ni]);  // Ab*Bs
                mma_bf16(acc[mi][ni], afb[mi], bfb[ni]);  // Ab*Bb
            }

        if (more) {
            asm volatile("cp.async.wait_group 0;\n");
            split_store(buf ^ 1);  // other buffer: no conflict with readers
            __syncthreads();
        }
    }

    #pragma unroll
    for (int mi = 0; mi < 4; mi++) {
        #pragma unroll
        for (int ni = 0; ni < 4; ni++) {
            int r = row0 + warp_m + mi * 16 + qr;
            int cc = col0 + warp_n + ni * 8 + qc * 2;
            float2 v0 = {acc[mi][ni][0], acc[mi][ni][1]};
            float2 v1 = {acc[mi][ni][2], acc[mi][ni][3]};
            *(float2*)&C[(size_t)r * N + cc] = v0;
            *(float2*)&C[(size_t)(r + 8) * N + cc] = v1;
        }
    }
}

// ------------------------------- CPL ----------------------------------------
__global__ void __launch_bounds__(1024) cpl_kernel(const float* __restrict__ bmax,
                                                   const int* __restrict__ bidx,
                                                   const float* __restrict__ s3,
                                                   const float* __restrict__ h3,
                                                   int* __restrict__ idx_out) {
    __shared__ float maxv[1024];
    __shared__ int   amax[1024];
    __shared__ float score[1024];
    __shared__ float key[1024];
    __shared__ int   packed[1024];

    int b = blockIdx.x;
    int c = threadIdx.x;

    {
        float act = fmaxf(bmax[b * 1024 + c] * s3[c] + h3[c], 0.f);
        maxv[c] = act;
        amax[c] = (act > 0.f) ? bidx[b * 1024 + c] : 0;
    }
    __syncthreads();

    int n = threadIdx.x;
    float sc = 0.f;
    for (int c2 = 0; c2 < 1024; c2++)
        if (amax[c2] == n) sc += maxv[c2];
    score[n] = sc;
    key[n] = (-sc) + CPL_EPS * (float)n;
    int m = __syncthreads_count(sc > 0.f);

    {
        bool any = (m == 0);
        bool mine = any || (score[n] > 0.f);
        if (mine) {
            float kn = key[n];
            int r = 0;
            for (int j = 0; j < 1024; j++) {
                bool sel = any || (score[j] > 0.f);
                if (sel) {
                    float kj = key[j];
                    if (kj < kn || (kj == kn && j < n)) r++;
                }
            }
            packed[r] = n;
        }
    }
    __syncthreads();

    if (threadIdx.x < CPLK) {
        int k = threadIdx.x;
        float mf = (m > 0) ? (float)m : (float)NPTS;
        int pos;
        if (mf >= (float)CPLK) {
            pos = k;
        } else {
            float lin = (float)k * (mf - 1.0f) / (float)(CPLK - 1);
            int p = (int)rintf(lin);
            int hi = (int)(mf - 1.0f);
            p = max(0, min(p, hi));
            pos = p;
        }
        idx_out[b * CPLK + k] = packed[pos];
    }
}

// ------------------------------ gather --------------------------------------
__global__ void __launch_bounds__(256) gather_kernel(const float* __restrict__ Z3,
                                                     const int* __restrict__ idx,
                                                     const float* __restrict__ s3,
                                                     const float* __restrict__ h3,
                                                     float* __restrict__ CR) {
    int i = blockIdx.x;
    int b = i >> 8;
    int src = idx[i];
    const float* p = Z3 + ((size_t)(b * NPTS + src) << 10);
    float* o = CR + ((size_t)i << 10);
    for (int c = threadIdx.x; c < 1024; c += 256)
        o[c] = fmaxf(p[c] * s3[c] + h3[c], 0.f);
}

// ------------------------------ max-pool ------------------------------------
__global__ void __launch_bounds__(256) maxpool_kernel(const float* __restrict__ ZC,
                                                      const float* __restrict__ sc,
                                                      const float* __restrict__ hc,
                                                      float* __restrict__ GF) {
    int b = blockIdx.x;
    int c = blockIdx.y * 256 + threadIdx.x;
    float s = sc[c], h = hc[c];
    const float* p = ZC + ((size_t)(b * CPLK) << 10) + c;
    float m = 0.f;
    for (int k = 0; k < CPLK; k += 4) {
        float v0 = p[(size_t)(k + 0) << 10];
        float v1 = p[(size_t)(k + 1) << 10];
        float v2 = p[(size_t)(k + 2) << 10];
        float v3 = p[(size_t)(k + 3) << 10];
        m = fmaxf(m, fmaxf(v0 * s + h, 0.f));
        m = fmaxf(m, fmaxf(v1 * s + h, 0.f));
        m = fmaxf(m, fmaxf(v2 * s + h, 0.f));
        m = fmaxf(m, fmaxf(v3 * s + h, 0.f));
    }
    GF[b * 1024 + c] = m;
}

// ------------------------------ FC (warp per output) ------------------------
__global__ void __launch_bounds__(256) fc_kernel(const float* __restrict__ Ain,
                                                 const float* __restrict__ W,
                                                 const float* __restrict__ bias,
                                                 const float* __restrict__ s,
                                                 const float* __restrict__ h,
                                                 float* __restrict__ out,
                                                 int B, int O, int Kin, int useAct) {
    int warp = (blockIdx.x * blockDim.x + threadIdx.x) >> 5;
    int lane = threadIdx.x & 31;
    if (warp >= B * O) return;
    int b = warp / O, o = warp - b * O;
    const float* a = Ain + (size_t)b * Kin;
    const float* w = W + (size_t)o * Kin;
    float acc = 0.f;
    for (int k = lane; k < Kin; k += 32) {
        float v = a[k];
        if (useAct) v = fmaxf(v * s[k] + h[k], 0.f);
        acc += v * w[k];
    }
    #pragma unroll
    for (int off = 16; off; off >>= 1)
        acc += __shfl_down_sync(0xffffffffu, acc, off);
    if (lane == 0) out[warp] = acc + bias[o];
}

// ------------------------------- driver --------------------------------------
extern "C" void kernel_launch(void* const* d_in, const int* in_sizes, int n_in,
                              void* d_out, int out_size) {
    const float* x     = (const float*)d_in[0];
    const float* W1    = (const float*)d_in[1];
    const float* g1    = (const float*)d_in[2];
    const float* b1    = (const float*)d_in[3];
    const float* W2    = (const float*)d_in[4];
    const float* g2    = (const float*)d_in[5];
    const float* b2    = (const float*)d_in[6];
    const float* W3    = (const float*)d_in[7];
    const float* g3    = (const float*)d_in[8];
    const float* b3    = (const float*)d_in[9];
    const float* Wc    = (const float*)d_in[10];
    const float* gc    = (const float*)d_in[11];
    const float* bc    = (const float*)d_in[12];
    const float* fc1w  = (const float*)d_in[13];
    const float* fc1b  = (const float*)d_in[14];
    const float* bn1g  = (const float*)d_in[15];
    const float* bn1b  = (const float*)d_in[16];
    const float* fc2w  = (const float*)d_in[17];
    const float* fc2b  = (const float*)d_in[18];
    const float* bn2g  = (const float*)d_in[19];
    const float* bn2b  = (const float*)d_in[20];
    const float* fc3w  = (const float*)d_in[21];
    const float* fc3b  = (const float*)d_in[22];
    float* out = (float*)d_out;

    float *Z1, *Z2, *Z3, *CR, *ZC, *PS, *PQ;
    float *S1, *H1, *S2, *H2, *S3, *H3, *SC, *HC, *SF1, *HF1, *SF2, *HF2;
    float *GF, *O1, *O2, *BMAX;
    int *IDX, *BIDX;
    cudaGetSymbolAddress((void**)&Z1, g_Z1);
    cudaGetSymbolAddress((void**)&Z2, g_Z2);
    cudaGetSymbolAddress((void**)&Z3, g_Z3);
    cudaGetSymbolAddress((void**)&CR, g_CR);
    cudaGetSymbolAddress((void**)&ZC, g_ZC);
    cudaGetSymbolAddress((void**)&PS, g_PS);
    cudaGetSymbolAddress((void**)&PQ, g_PQ);
    cudaGetSymbolAddress((void**)&S1, g_S1);  cudaGetSymbolAddress((void**)&H1, g_H1);
    cudaGetSymbolAddress((void**)&S2, g_S2);  cudaGetSymbolAddress((void**)&H2, g_H2);
    cudaGetSymbolAddress((void**)&S3, g_S3);  cudaGetSymbolAddress((void**)&H3, g_H3);
    cudaGetSymbolAddress((void**)&SC, g_SC);  cudaGetSymbolAddress((void**)&HC, g_HC);
    cudaGetSymbolAddress((void**)&SF1, g_SF1); cudaGetSymbolAddress((void**)&HF1, g_HF1);
    cudaGetSymbolAddress((void**)&SF2, g_SF2); cudaGetSymbolAddress((void**)&HF2, g_HF2);
    cudaGetSymbolAddress((void**)&GF, g_GF);
    cudaGetSymbolAddress((void**)&O1, g_O1);
    cudaGetSymbolAddress((void**)&O2, g_O2);
    cudaGetSymbolAddress((void**)&IDX, g_IDX);
    cudaGetSymbolAddress((void**)&BMAX, g_BMAX);
    cudaGetSymbolAddress((void**)&BIDX, g_BIDX);

    static bool attr_set = false;
    if (!attr_set) {
        cudaFuncSetAttribute(gemm3x_kernel<true>,
                             cudaFuncAttributeMaxDynamicSharedMemorySize, G3X_SMEM);
        cudaFuncSetAttribute(gemm3xbf16_kernel,
                             cudaFuncAttributeMaxDynamicSharedMemorySize, G3B_SMEM);
        attr_set = true;
    }

    dim3 st1b(32, 8);

    // layer 1: 3 -> 64
    l1_kernel<<<MROWS / 4, 256>>>(x, W1, Z1);
    colstats1<<<dim3(64 / 32, 64), st1b>>>(Z1, MROWS, 64, PS, PQ);
    colstats2<<<1, 256>>>(PS, PQ, MROWS, 64, g1, b1, S1, H1);

    // layer 2: 64 -> 128 (fp32, act fused on A load)
    sgemm_kernel<true><<<dim3(1, MROWS / 128), 256>>>(Z1, W2, S1, H1, Z2, MROWS, 128, 64);
    colstats1<<<dim3(128 / 32, 64), st1b>>>(Z2, MROWS, 128, PS, PQ);
    colstats2<<<1, 256>>>(PS, PQ, MROWS, 128, g2, b2, S2, H2);

    // layer 3: 128 -> 1024 (3xTF32 + cp.async, act fused at split)
    gemm3x_kernel<true><<<dim3(1024 / 128, MROWS / 128), 256, G3X_SMEM>>>(
        Z2, W3, S2, H2, Z3, MROWS, 1024, 128);
    colstats1_cpl<<<dim3(1024 / 32, 64), st1b>>>(Z3, PS, PQ, BMAX, BIDX);
    colstats2<<<4, 256>>>(PS, PQ, MROWS, 1024, g3, b3, S3, H3);

    // CPL index selection + gather (activation fused)
    cpl_kernel<<<BATCH, 1024>>>(BMAX, BIDX, S3, H3, IDX);
    gather_kernel<<<MCRIT, 256>>>(Z3, IDX, S3, H3, CR);

    // critical GEMM (bf16x3, ldmatrix, double-buffered planes): 1024 -> 1024
    gemm3xbf16_kernel<<<dim3(1024 / 128, MCRIT / 128), 256, G3B_SMEM>>>(
        CR, Wc, ZC, MCRIT, 1024, 1024);
    colstats1<<<dim3(1024 / 32, 64), st1b>>>(ZC, MCRIT, 1024, PS, PQ);
    colstats2<<<4, 256>>>(PS, PQ, MCRIT, 1024, gc, bc, SC, HC);

    // global max-pool over K (act fused)
    maxpool_kernel<<<dim3(BATCH, 4), 256>>>(ZC, SC, HC, GF);

    // fc1: 1024 -> 512
    fc_kernel<<<(BATCH * 512) / 8, 256>>>(GF, fc1w, fc1b, nullptr, nullptr, O1, BATCH, 512, 1024, 0);
    colstats_small<<<2, 256>>>(O1, BATCH, 512, bn1g, bn1b, SF1, HF1);

    // fc2: 512 -> 256 (act fused)
    fc_kernel<<<(BATCH * 256) / 8, 256>>>(O1, fc2w, fc2b, SF1, HF1, O2, BATCH, 256, 512, 1);
    colstats_small<<<1, 256>>>(O2, BATCH, 256, bn2g, bn2b, SF2, HF2);

    // fc3: 256 -> 40 -> d_out (act fused)
    fc_kernel<<<(BATCH * NCLS + 7) / 8, 256>>>(O2, fc3w, fc3b, SF2, HF2, out, BATCH, NCLS, 256, 1);
}